// round 15
// baseline (speedup 1.0000x reference)
#include <cuda_runtime.h>
#include <cuda_bf16.h>
#include <math.h>
#include <stdint.h>

#define NN 20000
#define EE 400000

// ---------------- mma.sync / ldmatrix / cp.async helpers ----------------
__device__ __forceinline__ uint32_t smem_u32(const void* p) {
    uint32_t a;
    asm("{ .reg .u64 t; cvta.to.shared.u64 t, %1; cvt.u32.u64 %0, t; }" : "=r"(a) : "l"(p));
    return a;
}
__device__ __forceinline__ void ldm_x4(uint32_t* r, uint32_t addr) {
    asm volatile("ldmatrix.sync.aligned.m8n8.x4.shared.b16 {%0,%1,%2,%3}, [%4];"
                 : "=r"(r[0]), "=r"(r[1]), "=r"(r[2]), "=r"(r[3]) : "r"(addr));
}
__device__ __forceinline__ void ldm_x4t(uint32_t* r, uint32_t addr) {
    asm volatile("ldmatrix.sync.aligned.m8n8.x4.trans.shared.b16 {%0,%1,%2,%3}, [%4];"
                 : "=r"(r[0]), "=r"(r[1]), "=r"(r[2]), "=r"(r[3]) : "r"(addr));
}
__device__ __forceinline__ void mma16816(float* c, const uint32_t* a, const uint32_t* b) {
    asm volatile(
        "mma.sync.aligned.m16n8k16.row.col.f32.bf16.bf16.f32 "
        "{%0,%1,%2,%3}, {%4,%5,%6,%7}, {%8,%9}, {%0,%1,%2,%3};"
        : "+f"(c[0]), "+f"(c[1]), "+f"(c[2]), "+f"(c[3])
        : "r"(a[0]), "r"(a[1]), "r"(a[2]), "r"(a[3]), "r"(b[0]), "r"(b[1]));
}
__device__ __forceinline__ void cp16(uint32_t smem, const void* gmem) {
    asm volatile("cp.async.ca.shared.global [%0], [%1], 16;"
                 :: "r"(smem), "l"(gmem) : "memory");
}
#define CP_COMMIT() asm volatile("cp.async.commit_group;" ::: "memory")
#define CP_WAIT0()  asm volatile("cp.async.wait_group 0;" ::: "memory")
__device__ __forceinline__ void barg(int id, int cnt) {
    asm volatile("bar.sync %0, %1;" :: "r"(id), "r"(cnt) : "memory");
}
__device__ __forceinline__ void split_bf16(float v, __nv_bfloat16& h, __nv_bfloat16& l) {
    h = __float2bfloat16(v);
    l = __float2bfloat16(v - __bfloat162float(h));
}
__device__ __forceinline__ uint32_t bfpack(__nv_bfloat16 a, __nv_bfloat16 b) {
    return ((uint32_t)*(uint16_t*)&b << 16) | (uint32_t)*(uint16_t*)&a;
}

// ---------------- scratch ----------------
#define CLS_OFF  786432
#define ENW1_OFF 1048576
#define ENW2_OFF 1052672
#define WTOTAL   1069056

__device__ float g_t1[(size_t)NN * 256];
__device__ float g_t2[(size_t)NN * 256];
__device__ float g_jk[(size_t)NN * 1024];
__device__ float g_z[(size_t)NN * 256];
__device__ float g_deg[NN];
__device__ float g_dis[NN];
__device__ int   g_cnt[NN];
__device__ int   g_cur[NN];
__device__ int   g_starts[NN + 1];
__device__ int   g_srcA[EE];
__device__ float g_wA[EE];
__device__ int   g_is64;
__device__ __nv_bfloat16 g_wsh[WTOTAL];
__device__ __nv_bfloat16 g_wsl[WTOTAL];

#define SEL_EXT 0
#define SEL_T1  1
#define SEL_T2  2
#define SEL_JK  3
#define SEL_Z   4

__device__ __forceinline__ const float* resolve_c(int sel, const float* ext, int off) {
    const float* p;
    switch (sel) {
        case SEL_T1: p = g_t1; break;
        case SEL_T2: p = g_t2; break;
        case SEL_JK: p = g_jk; break;
        case SEL_Z:  p = g_z;  break;
        default:     p = ext;  break;
    }
    return p + off;
}
__device__ __forceinline__ float* resolve_w(int sel, int off) {
    float* p;
    switch (sel) {
        case SEL_T1: p = g_t1; break;
        case SEL_T2: p = g_t2; break;
        case SEL_JK: p = g_jk; break;
        default:     p = g_z;  break;
    }
    return p + off;
}
__device__ __forceinline__ int idx_at(const void* ei, int i) {
    if (g_is64) return (int)((const long long*)ei)[i];
    return ((const int*)ei)[i];
}

__global__ void detect_kernel(const void* ei) {
    if (threadIdx.x == 0 && blockIdx.x == 0) {
        const long long* p = (const long long*)ei;
        int ok = 1;
        for (int i = 0; i < 64; i++) {
            long long v = p[i];
            if (v < 0 || v >= NN) ok = 0;
        }
        g_is64 = ok;
    }
}

__global__ void zero_kernel() {
    int n = blockIdx.x * blockDim.x + threadIdx.x;
    if (n < NN) { g_deg[n] = 0.f; g_cnt[n] = 0; g_cur[n] = 0; }
}

// ---------------- pre-split all weights to bf16 hi/lo ----------------
__global__ void split_weights_kernel(const float* __restrict__ cheb,
                                     const float* __restrict__ cls_w1,
                                     const float* __restrict__ en_w1,
                                     const float* __restrict__ en_w2)
{
    const int i = blockIdx.x * blockDim.x + threadIdx.x;
    if (i >= WTOTAL) return;
    float v;
    if (i < CLS_OFF) v = cheb[i];
    else if (i < ENW1_OFF) v = cls_w1[i - CLS_OFF];
    else if (i < ENW2_OFF) v = en_w1[i - ENW1_OFF];
    else v = en_w2[i - ENW2_OFF];
    __nv_bfloat16 h, l;
    split_bf16(v, h, l);
    g_wsh[i] = h;
    g_wsl[i] = l;
}

// ================= split-bf16 HMMA GEMM for node-side matrices (R14 form) ==========
// C = epi( sum_s A_s[M, K] @ W_s[K, 256] ); tile 128x128; K-chunk 32; double-buffered.
#define APAD 40
#define BPAD 136
#define HA_SZ (128 * APAD)
#define HB_SZ (32 * BPAD)
#define D_AH(b) ((b) * HA_SZ)
#define D_AL(b) (2 * HA_SZ + (b) * HA_SZ)
#define D_BH(b) (4 * HA_SZ + (b) * HB_SZ)
#define D_BL(b) (4 * HA_SZ + 2 * HB_SZ + (b) * HB_SZ)
#define HSMEM ((4 * HA_SZ + 4 * HB_SZ) * 2)   // 75776 bytes

template <int EPI>
__global__ __launch_bounds__(256, 2)
void hmma_kernel(int a0sel, const float* __restrict__ a0ext, int a0off, int lda0,
                 int w0off, int nseg, int cps, int ldw,
                 int csel, int coff, int ldc, int M,
                 const float* __restrict__ bias,
                 const float* __restrict__ bng, const float* __restrict__ bnb)
{
    extern __shared__ __nv_bfloat16 dsm[];

    const int tid = threadIdx.x;
    const int wid = tid >> 5;
    const int lane = tid & 31;
    const int bm = blockIdx.x * 128;
    const int bn = blockIdx.y * 128;
    const int mq = wid & 3;
    const int nh = wid >> 2;

    float acc[2][8][4];
#pragma unroll
    for (int mi = 0; mi < 2; mi++)
#pragma unroll
        for (int ni = 0; ni < 8; ni++)
#pragma unroll
            for (int q = 0; q < 4; q++) acc[mi][ni][q] = 0.f;

    const float* Aseg[3] = { resolve_c(a0sel, a0ext, a0off), g_t1, g_t2 };
    const int ldA[3] = { lda0, 256, 256 };

    const uint32_t base = smem_u32(dsm);
    const int a_m = (lane & 15);
    const int a_k = ((lane >> 4) << 3);
    const int b_row = (lane & 15);
    const int b_col8 = ((lane >> 4) << 3);

    const int sa_r = tid >> 1;
    const int sa_k0 = (tid & 1) * 16;
    const int sb_k = tid >> 3;
    const int sb_n0 = (tid & 7) * 16;

    const int nchunks = nseg * cps;

    auto stage = [&](int ch, int buf) {
        const int s = ch / cps;
        const int kk = (ch % cps) * 32;
        const float* A = Aseg[s];
        const int lda = ldA[s];
        {
            const size_t so = (size_t)w0off + (size_t)s * 65536 +
                              (size_t)(kk + sb_k) * ldw + bn + sb_n0;
            const uint32_t o = base + (uint32_t)(D_BH(buf) + sb_k * BPAD + sb_n0) * 2;
            const uint32_t o2 = base + (uint32_t)(D_BL(buf) + sb_k * BPAD + sb_n0) * 2;
            cp16(o, g_wsh + so);
            cp16(o + 16, g_wsh + so + 8);
            cp16(o2, g_wsl + so);
            cp16(o2 + 16, g_wsl + so + 8);
        }
        {
            int gr = bm + sa_r; gr = (gr < M) ? gr : (M - 1);
            const float4* src = (const float4*)(A + (size_t)gr * lda + kk + sa_k0);
            __nv_bfloat16* Ah = dsm + D_AH(buf);
            __nv_bfloat16* Al = dsm + D_AL(buf);
#pragma unroll
            for (int q = 0; q < 4; q++) {
                const float4 v = src[q];
                __nv_bfloat16 h0, l0, h1, l1, h2, l2, h3, l3;
                split_bf16(v.x, h0, l0); split_bf16(v.y, h1, l1);
                split_bf16(v.z, h2, l2); split_bf16(v.w, h3, l3);
                const int o = sa_r * APAD + sa_k0 + q * 4;
                *(uint2*)&Ah[o] = make_uint2(bfpack(h0, h1), bfpack(h2, h3));
                *(uint2*)&Al[o] = make_uint2(bfpack(l0, l1), bfpack(l2, l3));
            }
        }
    };

    stage(0, 0);
    CP_COMMIT();
    CP_WAIT0();
    __syncthreads();

    for (int ch = 0; ch < nchunks; ch++) {
        const int cur = ch & 1;
        if (ch + 1 < nchunks) {
            stage(ch + 1, cur ^ 1);
            CP_COMMIT();
        }

        const uint32_t AhB = base + D_AH(cur) * 2;
        const uint32_t AlB = base + D_AL(cur) * 2;
        const uint32_t BhB = base + D_BH(cur) * 2;
        const uint32_t BlB = base + D_BL(cur) * 2;

#pragma unroll
        for (int ks = 0; ks < 32; ks += 16) {
            uint32_t ahi[2][4], alo[2][4];
#pragma unroll
            for (int mi = 0; mi < 2; mi++) {
                const int m = mq * 32 + mi * 16 + a_m;
                const uint32_t off = (uint32_t)(m * APAD + ks + a_k) * 2;
                ldm_x4(ahi[mi], AhB + off);
                ldm_x4(alo[mi], AlB + off);
            }
#pragma unroll
            for (int nip = 0; nip < 4; nip++) {
                uint32_t bh4[4], bl4[4];
                const uint32_t off =
                    (uint32_t)((ks + b_row) * BPAD + nh * 64 + nip * 16 + b_col8) * 2;
                ldm_x4t(bh4, BhB + off);
                ldm_x4t(bl4, BlB + off);
#pragma unroll
                for (int half = 0; half < 2; half++) {
                    const int ni = nip * 2 + half;
#pragma unroll
                    for (int mi = 0; mi < 2; mi++) {
                        mma16816(acc[mi][ni], ahi[mi], bh4 + half * 2);
                        mma16816(acc[mi][ni], ahi[mi], bl4 + half * 2);
                        mma16816(acc[mi][ni], alo[mi], bh4 + half * 2);
                    }
                }
            }
        }
        CP_WAIT0();
        __syncthreads();
    }

    float* C = resolve_w(csel, coff);
    const float inv = rsqrtf(1.0f + 1e-5f);
    const int r0b = bm + mq * 32 + (lane >> 2);
    const int cb = bn + nh * 64 + (lane & 3) * 2;
#pragma unroll
    for (int ni = 0; ni < 8; ni++) {
        const int col = cb + ni * 8;
        float b0 = 0.f, b1 = 0.f, s0 = 1.f, s1 = 1.f, o0 = 0.f, o1 = 0.f;
        if (EPI == 1) {
            b0 = __ldg(bias + col); b1 = __ldg(bias + col + 1);
            s0 = __ldg(bng + col) * inv; s1 = __ldg(bng + col + 1) * inv;
            o0 = __ldg(bnb + col); o1 = __ldg(bnb + col + 1);
        }
#pragma unroll
        for (int mi = 0; mi < 2; mi++) {
#pragma unroll
            for (int half = 0; half < 2; half++) {
                const int r = r0b + mi * 16 + half * 8;
                if (r < M) {
                    float x0 = acc[mi][ni][half * 2 + 0];
                    float x1 = acc[mi][ni][half * 2 + 1];
                    if (EPI == 1) {
                        x0 = fmaxf(x0 + b0, 0.f) * s0 + o0;
                        x1 = fmaxf(x1 + b1, 0.f) * s1 + o1;
                    } else {
                        x0 = fmaxf(x0, 0.f);
                        x1 = fmaxf(x1, 0.f);
                    }
                    *(float2*)(C + (size_t)r * ldc + col) = make_float2(x0, x1);
                }
            }
        }
    }
}

// ================= split-bf16 HMMA fused edge encoder (512 thr, 2 tiles/CTA) =======
#define EAPAD 72
#define EBPAD 136
#define EMPAD 136
#define ETILES (EE / 64)
#define EPAIRS (ETILES / 2)
#define EO_W1H 0
#define EO_W1L 8704
#define EO_W2H 17408
#define EO_W2L 52224
#define EG_SZ  54784
#define EO_XH(g)  (87040 + (g) * EG_SZ)
#define EO_XL(g)  (EO_XH(g) + 9216)
#define EO_MH(g)  (EO_XL(g) + 9216)
#define EO_ML(g)  (EO_MH(g) + 17408)
#define EO_RED(g) (EO_ML(g) + 17408)
#define EO_B1  196608
#define EO_SC  197120
#define EO_OF  197632
#define EO_B2  198144
#define ESMEM  198656

__global__ __launch_bounds__(512)
void edge_hmma_kernel(const float* __restrict__ edgenet,
                      const float* __restrict__ b1v, const float* __restrict__ gam,
                      const float* __restrict__ bet, const float* __restrict__ b2v,
                      float* __restrict__ ew)
{
    extern __shared__ char sm[];
    const int tid = threadIdx.x;
    const int g = tid >> 8;
    const int gt = tid & 255;
    const int wid = gt >> 5, lane = gt & 31;
    const int mq = wid & 3, nh = wid >> 2;
    const float inv = rsqrtf(1.f + 1e-5f);

    __nv_bfloat16* W1h = (__nv_bfloat16*)(sm + EO_W1H);
    __nv_bfloat16* W1l = (__nv_bfloat16*)(sm + EO_W1L);
    __nv_bfloat16* W2h = (__nv_bfloat16*)(sm + EO_W2H);
    __nv_bfloat16* W2l = (__nv_bfloat16*)(sm + EO_W2L);
    __nv_bfloat16* Xh = (__nv_bfloat16*)(sm + EO_XH(g));
    __nv_bfloat16* Xl = (__nv_bfloat16*)(sm + EO_XL(g));
    __nv_bfloat16* Mh = (__nv_bfloat16*)(sm + EO_MH(g));
    __nv_bfloat16* Ml = (__nv_bfloat16*)(sm + EO_ML(g));
    float* red = (float*)(sm + EO_RED(g));
    float* b1s = (float*)(sm + EO_B1);
    float* scs = (float*)(sm + EO_SC);
    float* ofs = (float*)(sm + EO_OF);
    float* b2s = (float*)(sm + EO_B2);

    if (tid < 256) {
        const int r = tid >> 3, c0 = (tid & 7) * 16;
        const size_t so = (size_t)ENW1_OFF + r * 128 + c0;
        const int o = r * EBPAD + c0;
        *(uint4*)&W1h[o] = *(const uint4*)(g_wsh + so);
        *(uint4*)&W1h[o + 8] = *(const uint4*)(g_wsh + so + 8);
        *(uint4*)&W1l[o] = *(const uint4*)(g_wsl + so);
        *(uint4*)&W1l[o + 8] = *(const uint4*)(g_wsl + so + 8);
    }
    {
        const int r = tid >> 2, c0 = (tid & 3) * 32;
        const size_t so = (size_t)ENW2_OFF + r * 128 + c0;
#pragma unroll
        for (int q = 0; q < 4; q++) {
            *(uint4*)&W2h[r * EBPAD + c0 + q * 8] = *(const uint4*)(g_wsh + so + q * 8);
            *(uint4*)&W2l[r * EBPAD + c0 + q * 8] = *(const uint4*)(g_wsl + so + q * 8);
        }
    }
    if (tid < 128) {
        b1s[tid] = b1v[tid];
        scs[tid] = gam[tid] * inv;
        ofs[tid] = bet[tid];
        b2s[tid] = b2v[tid];
    }
    __syncthreads();

    const uint32_t XhB = smem_u32(Xh), XlB = smem_u32(Xl);
    const uint32_t W1hB = smem_u32(W1h), W1lB = smem_u32(W1l);
    const uint32_t W2hB = smem_u32(W2h), W2lB = smem_u32(W2l);
    const uint32_t MhB = smem_u32(Mh), MlB = smem_u32(Ml);

    const int a_m = lane & 15, a_k = (lane >> 4) << 3;
    const int b_row = lane & 15, b_col8 = (lane >> 4) << 3;
    const int rr = lane >> 2;
    const int cb = nh * 64 + (lane & 3) * 2;
    const int bid = g + 1;

    for (int pair = blockIdx.x; pair < EPAIRS; pair += gridDim.x) {
        const int t = pair * 2 + g;
        {
            const int r = gt >> 2, c0 = (gt & 3) * 16;
            const float4* src = (const float4*)(edgenet + (size_t)(t * 64 + r) * 64 + c0);
#pragma unroll
            for (int q = 0; q < 4; q++) {
                const float4 v = src[q];
                __nv_bfloat16 h0, l0, h1, l1, h2, l2, h3, l3;
                split_bf16(v.x, h0, l0); split_bf16(v.y, h1, l1);
                split_bf16(v.z, h2, l2); split_bf16(v.w, h3, l3);
                const int o = r * EAPAD + c0 + q * 4;
                *(uint2*)&Xh[o] = make_uint2(bfpack(h0, h1), bfpack(h2, h3));
                *(uint2*)&Xl[o] = make_uint2(bfpack(l0, l1), bfpack(l2, l3));
            }
        }
        barg(bid, 256);

        float hacc[2][8][4];
#pragma unroll
        for (int half = 0; half < 2; half++) {
            float macc[8][4];
#pragma unroll
            for (int ni = 0; ni < 8; ni++)
#pragma unroll
                for (int q = 0; q < 4; q++) macc[ni][q] = 0.f;
#pragma unroll
            for (int ks = 0; ks < 32; ks += 16) {
                uint32_t ah[4], al[4];
                const uint32_t aoff =
                    (uint32_t)((mq * 16 + a_m) * EAPAD + half * 32 + ks + a_k) * 2;
                ldm_x4(ah, XhB + aoff);
                ldm_x4(al, XlB + aoff);
#pragma unroll
                for (int nip = 0; nip < 4; nip++) {
                    uint32_t bh4[4], bl4[4];
                    const uint32_t boff =
                        (uint32_t)((ks + b_row) * EBPAD + nh * 64 + nip * 16 + b_col8) * 2;
                    ldm_x4t(bh4, W1hB + boff);
                    ldm_x4t(bl4, W1lB + boff);
#pragma unroll
                    for (int hh = 0; hh < 2; hh++) {
                        const int ni = nip * 2 + hh;
                        mma16816(macc[ni], ah, bh4 + hh * 2);
                        mma16816(macc[ni], ah, bl4 + hh * 2);
                        mma16816(macc[ni], al, bh4 + hh * 2);
                    }
                }
            }
            barg(bid, 256);
            {
                const int r0 = mq * 16 + rr;
#pragma unroll
                for (int ni = 0; ni < 8; ni++) {
                    const int col = cb + ni * 8;
                    const float s0 = scs[col], s1 = scs[col + 1];
                    const float bb0 = b1s[col], bb1 = b1s[col + 1];
                    const float o0 = ofs[col], o1 = ofs[col + 1];
                    const float v00 = fmaxf(macc[ni][0] + bb0, 0.f) * s0 + o0;
                    const float v01 = fmaxf(macc[ni][1] + bb1, 0.f) * s1 + o1;
                    const float v10 = fmaxf(macc[ni][2] + bb0, 0.f) * s0 + o0;
                    const float v11 = fmaxf(macc[ni][3] + bb1, 0.f) * s1 + o1;
                    __nv_bfloat16 h0, l0, h1, l1;
                    split_bf16(v00, h0, l0); split_bf16(v01, h1, l1);
                    *(uint32_t*)&Mh[r0 * EMPAD + col] = bfpack(h0, h1);
                    *(uint32_t*)&Ml[r0 * EMPAD + col] = bfpack(l0, l1);
                    split_bf16(v10, h0, l0); split_bf16(v11, h1, l1);
                    *(uint32_t*)&Mh[(r0 + 8) * EMPAD + col] = bfpack(h0, h1);
                    *(uint32_t*)&Ml[(r0 + 8) * EMPAD + col] = bfpack(l0, l1);
                }
            }
            barg(bid, 256);
#pragma unroll
            for (int ni = 0; ni < 8; ni++)
#pragma unroll
                for (int q = 0; q < 4; q++) hacc[half][ni][q] = 0.f;
#pragma unroll
            for (int ks = 0; ks < 128; ks += 16) {
                uint32_t ah[4], al[4];
                const uint32_t aoff = (uint32_t)((mq * 16 + a_m) * EMPAD + ks + a_k) * 2;
                ldm_x4(ah, MhB + aoff);
                ldm_x4(al, MlB + aoff);
#pragma unroll
                for (int nip = 0; nip < 4; nip++) {
                    uint32_t bh4[4], bl4[4];
                    const uint32_t boff =
                        (uint32_t)((ks + b_row) * EBPAD + nh * 64 + nip * 16 + b_col8) * 2;
                    ldm_x4t(bh4, W2hB + boff);
                    ldm_x4t(bl4, W2lB + boff);
#pragma unroll
                    for (int hh = 0; hh < 2; hh++) {
                        const int ni = nip * 2 + hh;
                        mma16816(hacc[half][ni], ah, bh4 + hh * 2);
                        mma16816(hacc[half][ni], ah, bl4 + hh * 2);
                        mma16816(hacc[half][ni], al, bh4 + hh * 2);
                    }
                }
            }
        }

        float p11a = 0.f, p22a = 0.f, p12a = 0.f;
        float p11b = 0.f, p22b = 0.f, p12b = 0.f;
#pragma unroll
        for (int ni = 0; ni < 8; ni++) {
            const int col = cb + ni * 8;
#pragma unroll
            for (int q = 0; q < 2; q++) {
                const float bb = b2s[col + q];
                const float h0a = hacc[0][ni][q] + bb;
                const float h1a = hacc[1][ni][q] + bb;
                const float h0b = hacc[0][ni][q + 2] + bb;
                const float h1b = hacc[1][ni][q + 2] + bb;
                p11a += h0a * h0a; p22a += h1a * h1a; p12a += h0a * h1a;
                p11b += h0b * h0b; p22b += h1b * h1b; p12b += h0b * h1b;
            }
        }
#pragma unroll
        for (int m = 1; m <= 2; m <<= 1) {
            p11a += __shfl_xor_sync(0xffffffffu, p11a, m);
            p22a += __shfl_xor_sync(0xffffffffu, p22a, m);
            p12a += __shfl_xor_sync(0xffffffffu, p12a, m);
            p11b += __shfl_xor_sync(0xffffffffu, p11b, m);
            p22b += __shfl_xor_sync(0xffffffffu, p22b, m);
            p12b += __shfl_xor_sync(0xffffffffu, p12b, m);
        }
        if ((lane & 3) == 0) {
            const int r0 = mq * 16 + rr;
            red[0 * 128 + nh * 64 + r0] = p11a;
            red[1 * 128 + nh * 64 + r0] = p22a;
            red[2 * 128 + nh * 64 + r0] = p12a;
            red[0 * 128 + nh * 64 + r0 + 8] = p11b;
            red[1 * 128 + nh * 64 + r0 + 8] = p22b;
            red[2 * 128 + nh * 64 + r0 + 8] = p12b;
        }
        barg(bid, 256);
        if (gt < 64) {
            const float s11 = red[0 * 128 + gt] + red[0 * 128 + 64 + gt];
            const float s22 = red[1 * 128 + gt] + red[1 * 128 + 64 + gt];
            const float s12 = red[2 * 128 + gt] + red[2 * 128 + 64 + gt];
            const float n1 = fmaxf(sqrtf(s11), 1e-8f);
            const float n2 = fmaxf(sqrtf(s22), 1e-8f);
            ew[t * 64 + gt] = (s12 / (n1 * n2) + 1.f) * 0.5f;
        }
        barg(bid, 256);
    }
}

// ---------------- CSR build ----------------
__global__ void degcnt_kernel(const void* __restrict__ ei, const float* __restrict__ ew)
{
    const int e = blockIdx.x * blockDim.x + threadIdx.x;
    if (e < EE) {
        const int row = idx_at(ei, e);
        const int col = idx_at(ei, e + EE);
        atomicAdd(&g_deg[row], ew[e]);
        atomicAdd(&g_cnt[col], 1);
    }
}

__global__ void dis_kernel()
{
    const int n = blockIdx.x * blockDim.x + threadIdx.x;
    if (n < NN) {
        const float d = g_deg[n];
        g_dis[n] = (d > 0.f) ? rsqrtf(fmaxf(d, 1e-30f)) : 0.f;
    }
}

__global__ void scan_kernel()
{
    __shared__ int sm[1024];
    __shared__ int carry;
    const int tid = threadIdx.x;
    if (tid == 0) carry = 0;
    __syncthreads();
    for (int base = 0; base < NN; base += 1024) {
        const int idx = base + tid;
        const int v = (idx < NN) ? g_cnt[idx] : 0;
        sm[tid] = v;
        __syncthreads();
        for (int off = 1; off < 1024; off <<= 1) {
            const int t = (tid >= off) ? sm[tid - off] : 0;
            __syncthreads();
            sm[tid] += t;
            __syncthreads();
        }
        const int c = carry;
        if (idx < NN) g_starts[idx] = c + sm[tid] - v;
        const int tot = sm[1023];
        __syncthreads();
        if (tid == 0) carry = c + tot;
        __syncthreads();
    }
    if (tid == 0) g_starts[NN] = carry;
}

__global__ void fill_kernel(const void* __restrict__ ei, const float* __restrict__ ew)
{
    const int e = blockIdx.x * blockDim.x + threadIdx.x;
    if (e < EE) {
        const int row = idx_at(ei, e);
        const int col = idx_at(ei, e + EE);
        const int p = g_starts[col] + atomicAdd(&g_cur[col], 1);
        g_srcA[p] = row;
        g_wA[p] = -g_dis[row] * ew[e] * g_dis[col];
    }
}

// ---------------- sparse propagation (fp32, 4-edge unroll for MLP=4) ----------------
__global__ __launch_bounds__(64)
void prop_kernel(int xsel, const float* __restrict__ xext, int xoff, int ldx,
                 int x0sel, const float* __restrict__ x0ext, int x0off, int ldx0,
                 int osel, int mode)
{
    const float* X  = resolve_c(xsel, xext, xoff);
    const float* X0 = (mode ? resolve_c(x0sel, x0ext, x0off) : nullptr);
    float* out = resolve_w(osel, 0);
    const int n = blockIdx.x;
    const int t = threadIdx.x;
    const int s0 = g_starts[n];
    const int s1 = g_starts[n + 1];
    const int c4 = t << 2;
    float4 a0 = make_float4(0, 0, 0, 0);
    float4 a1 = make_float4(0, 0, 0, 0);
    float4 a2 = make_float4(0, 0, 0, 0);
    float4 a3 = make_float4(0, 0, 0, 0);
    int i = s0;
    for (; i + 3 < s1; i += 4) {
        const int r0 = g_srcA[i];
        const int r1 = g_srcA[i + 1];
        const int r2 = g_srcA[i + 2];
        const int r3 = g_srcA[i + 3];
        const float w0 = g_wA[i];
        const float w1 = g_wA[i + 1];
        const float w2 = g_wA[i + 2];
        const float w3 = g_wA[i + 3];
        const float4 x0 = *(const float4*)(X + (size_t)r0 * ldx + c4);
        const float4 x1 = *(const float4*)(X + (size_t)r1 * ldx + c4);
        const float4 x2 = *(const float4*)(X + (size_t)r2 * ldx + c4);
        const float4 x3 = *(const float4*)(X + (size_t)r3 * ldx + c4);
        a0.x += w0 * x0.x; a0.y += w0 * x0.y; a0.z += w0 * x0.z; a0.w += w0 * x0.w;
        a1.x += w1 * x1.x; a1.y += w1 * x1.y; a1.z += w1 * x1.z; a1.w += w1 * x1.w;
        a2.x += w2 * x2.x; a2.y += w2 * x2.y; a2.z += w2 * x2.z; a2.w += w2 * x2.w;
        a3.x += w3 * x3.x; a3.y += w3 * x3.y; a3.z += w3 * x3.z; a3.w += w3 * x3.w;
    }
    for (; i < s1; i++) {
        const int r0 = g_srcA[i];
        const float w0 = g_wA[i];
        const float4 x0 = *(const float4*)(X + (size_t)r0 * ldx + c4);
        a0.x += w0 * x0.x; a0.y += w0 * x0.y; a0.z += w0 * x0.z; a0.w += w0 * x0.w;
    }
    float4 r = make_float4((a0.x + a1.x) + (a2.x + a3.x),
                           (a0.y + a1.y) + (a2.y + a3.y),
                           (a0.z + a1.z) + (a2.z + a3.z),
                           (a0.w + a1.w) + (a2.w + a3.w));
    if (mode) {
        const float4 xv = *(const float4*)(X0 + (size_t)n * ldx0 + c4);
        r.x = 2.f * r.x - xv.x;
        r.y = 2.f * r.y - xv.y;
        r.z = 2.f * r.z - xv.z;
        r.w = 2.f * r.w - xv.w;
    }
    *(float4*)(out + (size_t)n * 256 + c4) = r;
}

// ---------------- final tiny GEMM: logit = z @ cls_w2 + b2 ----------------
__global__ void logits_kernel(const float* __restrict__ w2, const float* __restrict__ b2,
                              float* __restrict__ out)
{
    const int n = blockIdx.x * 8 + (threadIdx.x >> 5);
    const int lane = threadIdx.x & 31;
    if (n >= NN) return;
    float a0 = 0.f, a1 = 0.f;
    const float* z = g_z + (size_t)n * 256;
    for (int i = lane; i < 256; i += 32) {
        const float zv = z[i];
        a0 += zv * w2[2 * i];
        a1 += zv * w2[2 * i + 1];
    }
#pragma unroll
    for (int off = 16; off > 0; off >>= 1) {
        a0 += __shfl_xor_sync(0xffffffffu, a0, off);
        a1 += __shfl_xor_sync(0xffffffffu, a1, off);
    }
    if (lane == 0) {
        out[2 * n] = a0 + b2[0];
        out[2 * n + 1] = a1 + b2[1];
    }
}

// ---------------- launch ----------------
extern "C" void kernel_launch(void* const* d_in, const int* in_sizes, int n_in,
                              void* d_out, int out_size)
{
    (void)in_sizes; (void)n_in; (void)out_size;
    const float* features = (const float*)d_in[0];
    const void*  ei       = d_in[1];
    const float* edgenet  = (const float*)d_in[2];
    const float* cheb     = (const float*)d_in[3];
    const float* en_w1    = (const float*)d_in[4];
    const float* en_b1    = (const float*)d_in[5];
    const float* en_g1    = (const float*)d_in[6];
    const float* en_be1   = (const float*)d_in[7];
    const float* en_w2    = (const float*)d_in[8];
    const float* en_b2    = (const float*)d_in[9];
    const float* cls_w1   = (const float*)d_in[10];
    const float* cls_b1   = (const float*)d_in[11];
    const float* cls_g    = (const float*)d_in[12];
    const float* cls_b    = (const float*)d_in[13];
    const float* cls_w2   = (const float*)d_in[14];
    const float* cls_b2   = (const float*)d_in[15];
    float* out = (float*)d_out;
    float* ew  = out + NN * 2;

    cudaFuncSetAttribute(edge_hmma_kernel,
                         cudaFuncAttributeMaxDynamicSharedMemorySize, ESMEM);
    cudaFuncSetAttribute(hmma_kernel<1>,
                         cudaFuncAttributeMaxDynamicSharedMemorySize, HSMEM);
    cudaFuncSetAttribute(hmma_kernel<2>,
                         cudaFuncAttributeMaxDynamicSharedMemorySize, HSMEM);

    detect_kernel<<<1, 32>>>(ei);
    zero_kernel<<<(NN + 255) / 256, 256>>>();
    split_weights_kernel<<<(WTOTAL + 255) / 256, 256>>>(cheb, cls_w1, en_w1, en_w2);

    edge_hmma_kernel<<<148, 512, ESMEM>>>(edgenet, en_b1, en_g1, en_be1, en_b2, ew);

    degcnt_kernel<<<(EE + 255) / 256, 256>>>(ei, ew);
    dis_kernel<<<(NN + 255) / 256, 256>>>();
    scan_kernel<<<1, 1024>>>();
    fill_kernel<<<(EE + 255) / 256, 256>>>(ei, ew);

    const int mtiles = (NN + 127) / 128;
    for (int l = 0; l < 4; l++) {
        const int xsel = (l == 0) ? SEL_EXT : SEL_JK;
        const int xoff = (l == 0) ? 0 : (l - 1) * 256;
        const int ldx  = (l == 0) ? 256 : 1024;
        prop_kernel<<<NN, 64>>>(xsel, features, xoff, ldx,
                                0, nullptr, 0, 0, SEL_T1, 0);
        prop_kernel<<<NN, 64>>>(SEL_T1, nullptr, 0, 256,
                                xsel, features, xoff, ldx, SEL_T2, 1);
        dim3 gC(mtiles, 2);
        hmma_kernel<2><<<gC, 256, HSMEM>>>(
            xsel, features, xoff, ldx,
            (l * 3) * 65536, 3, 8, 256,
            SEL_JK, l * 256, 1024, NN,
            nullptr, nullptr, nullptr);
    }

    dim3 gZ(mtiles, 2);
    hmma_kernel<1><<<gZ, 256, HSMEM>>>(
        SEL_JK, nullptr, 0, 1024,
        CLS_OFF, 1, 32, 256,
        SEL_Z, 0, 256, NN,
        cls_b1, cls_g, cls_b);
    logits_kernel<<<NN / 8, 256>>>(cls_w2, cls_b2, out);
}

// round 16
// speedup vs baseline: 1.0284x; 1.0284x over previous
#include <cuda_runtime.h>
#include <cuda_bf16.h>
#include <math.h>
#include <stdint.h>

#define NN 20000
#define EE 400000

// ---------------- mma.sync / ldmatrix / cp.async helpers ----------------
__device__ __forceinline__ uint32_t smem_u32(const void* p) {
    uint32_t a;
    asm("{ .reg .u64 t; cvta.to.shared.u64 t, %1; cvt.u32.u64 %0, t; }" : "=r"(a) : "l"(p));
    return a;
}
__device__ __forceinline__ void ldm_x4(uint32_t* r, uint32_t addr) {
    asm volatile("ldmatrix.sync.aligned.m8n8.x4.shared.b16 {%0,%1,%2,%3}, [%4];"
                 : "=r"(r[0]), "=r"(r[1]), "=r"(r[2]), "=r"(r[3]) : "r"(addr));
}
__device__ __forceinline__ void ldm_x4t(uint32_t* r, uint32_t addr) {
    asm volatile("ldmatrix.sync.aligned.m8n8.x4.trans.shared.b16 {%0,%1,%2,%3}, [%4];"
                 : "=r"(r[0]), "=r"(r[1]), "=r"(r[2]), "=r"(r[3]) : "r"(addr));
}
__device__ __forceinline__ void mma16816(float* c, const uint32_t* a, const uint32_t* b) {
    asm volatile(
        "mma.sync.aligned.m16n8k16.row.col.f32.bf16.bf16.f32 "
        "{%0,%1,%2,%3}, {%4,%5,%6,%7}, {%8,%9}, {%0,%1,%2,%3};"
        : "+f"(c[0]), "+f"(c[1]), "+f"(c[2]), "+f"(c[3])
        : "r"(a[0]), "r"(a[1]), "r"(a[2]), "r"(a[3]), "r"(b[0]), "r"(b[1]));
}
__device__ __forceinline__ void cp16(uint32_t smem, const void* gmem) {
    asm volatile("cp.async.ca.shared.global [%0], [%1], 16;"
                 :: "r"(smem), "l"(gmem) : "memory");
}
#define CP_COMMIT() asm volatile("cp.async.commit_group;" ::: "memory")
#define CP_WAIT0()  asm volatile("cp.async.wait_group 0;" ::: "memory")
__device__ __forceinline__ void barg(int id, int cnt) {
    asm volatile("bar.sync %0, %1;" :: "r"(id), "r"(cnt) : "memory");
}
__device__ __forceinline__ void split_bf16(float v, __nv_bfloat16& h, __nv_bfloat16& l) {
    h = __float2bfloat16(v);
    l = __float2bfloat16(v - __bfloat162float(h));
}
__device__ __forceinline__ uint32_t bfpack(__nv_bfloat16 a, __nv_bfloat16 b) {
    return ((uint32_t)*(uint16_t*)&b << 16) | (uint32_t)*(uint16_t*)&a;
}

// ---------------- scratch ----------------
#define CLS_OFF  786432
#define ENW1_OFF 1048576
#define ENW2_OFF 1052672
#define WTOTAL   1069056

__device__ float g_t1[(size_t)NN * 256];
__device__ float g_t2[(size_t)NN * 256];
__device__ float g_jk[(size_t)NN * 1024];
__device__ float g_deg[NN];
__device__ float g_dis[NN];
__device__ int   g_cnt[NN];
__device__ int   g_cur[NN];
__device__ int   g_starts[NN + 1];
__device__ int   g_srcA[EE];
__device__ float g_wA[EE];
__device__ int   g_is64;
__device__ __nv_bfloat16 g_wsh[WTOTAL];
__device__ __nv_bfloat16 g_wsl[WTOTAL];

#define SEL_EXT 0
#define SEL_T1  1
#define SEL_T2  2
#define SEL_JK  3

__device__ __forceinline__ const float* resolve_c(int sel, const float* ext, int off) {
    const float* p;
    switch (sel) {
        case SEL_T1: p = g_t1; break;
        case SEL_T2: p = g_t2; break;
        case SEL_JK: p = g_jk; break;
        default:     p = ext;  break;
    }
    return p + off;
}
__device__ __forceinline__ float* resolve_w(int sel, int off) {
    float* p;
    switch (sel) {
        case SEL_T1: p = g_t1; break;
        case SEL_T2: p = g_t2; break;
        default:     p = g_jk; break;
    }
    return p + off;
}
__device__ __forceinline__ int idx_at(const void* ei, int i) {
    if (g_is64) return (int)((const long long*)ei)[i];
    return ((const int*)ei)[i];
}

__global__ void detect_kernel(const void* ei) {
    if (threadIdx.x == 0 && blockIdx.x == 0) {
        const long long* p = (const long long*)ei;
        int ok = 1;
        for (int i = 0; i < 64; i++) {
            long long v = p[i];
            if (v < 0 || v >= NN) ok = 0;
        }
        g_is64 = ok;
    }
}

// zero accumulators + init logits output with bias b2
__global__ void zero_kernel(float* __restrict__ outp, const float* __restrict__ b2)
{
    int n = blockIdx.x * blockDim.x + threadIdx.x;
    if (n < NN) {
        g_deg[n] = 0.f; g_cnt[n] = 0; g_cur[n] = 0;
        outp[2 * n] = b2[0];
        outp[2 * n + 1] = b2[1];
    }
}

// ---------------- pre-split all weights to bf16 hi/lo ----------------
__global__ void split_weights_kernel(const float* __restrict__ cheb,
                                     const float* __restrict__ cls_w1,
                                     const float* __restrict__ en_w1,
                                     const float* __restrict__ en_w2)
{
    const int i = blockIdx.x * blockDim.x + threadIdx.x;
    if (i >= WTOTAL) return;
    float v;
    if (i < CLS_OFF) v = cheb[i];
    else if (i < ENW1_OFF) v = cls_w1[i - CLS_OFF];
    else if (i < ENW2_OFF) v = en_w1[i - ENW1_OFF];
    else v = en_w2[i - ENW2_OFF];
    __nv_bfloat16 h, l;
    split_bf16(v, h, l);
    g_wsh[i] = h;
    g_wsl[i] = l;
}

// ================= split-bf16 HMMA GEMM for node-side matrices ==========
// C = epi( sum_s A_s[M, K] @ W_s[K, 256] ); tile 128x128; K-chunk 32; double-buffered.
// EPI 1: relu(x+bias)*bn+bnb, then fused logits: atomicAdd(out, z @ w2).
// EPI 2: relu -> C (g_jk at coff).
#define APAD 40
#define BPAD 136
#define HA_SZ (128 * APAD)
#define HB_SZ (32 * BPAD)
#define D_AH(b) ((b) * HA_SZ)
#define D_AL(b) (2 * HA_SZ + (b) * HA_SZ)
#define D_BH(b) (4 * HA_SZ + (b) * HB_SZ)
#define D_BL(b) (4 * HA_SZ + 2 * HB_SZ + (b) * HB_SZ)
#define HSMEM ((4 * HA_SZ + 4 * HB_SZ) * 2)   // 75776 bytes

template <int EPI>
__global__ __launch_bounds__(256, 2)
void hmma_kernel(int a0sel, const float* __restrict__ a0ext, int a0off, int lda0,
                 int w0off, int nseg, int cps, int ldw,
                 int csel, int coff, int ldc, int M,
                 const float* __restrict__ bias,
                 const float* __restrict__ bng, const float* __restrict__ bnb,
                 const float* __restrict__ w2, float* __restrict__ outp)
{
    extern __shared__ __nv_bfloat16 dsm[];

    const int tid = threadIdx.x;
    const int wid = tid >> 5;
    const int lane = tid & 31;
    const int bm = blockIdx.x * 128;
    const int bn = blockIdx.y * 128;
    const int mq = wid & 3;
    const int nh = wid >> 2;

    float acc[2][8][4];
#pragma unroll
    for (int mi = 0; mi < 2; mi++)
#pragma unroll
        for (int ni = 0; ni < 8; ni++)
#pragma unroll
            for (int q = 0; q < 4; q++) acc[mi][ni][q] = 0.f;

    const float* Aseg[3] = { resolve_c(a0sel, a0ext, a0off), g_t1, g_t2 };
    const int ldA[3] = { lda0, 256, 256 };

    const uint32_t base = smem_u32(dsm);
    const int a_m = (lane & 15);
    const int a_k = ((lane >> 4) << 3);
    const int b_row = (lane & 15);
    const int b_col8 = ((lane >> 4) << 3);

    const int sa_r = tid >> 1;
    const int sa_k0 = (tid & 1) * 16;
    const int sb_k = tid >> 3;
    const int sb_n0 = (tid & 7) * 16;

    const int nchunks = nseg * cps;

    auto stage = [&](int ch, int buf) {
        const int s = ch / cps;
        const int kk = (ch % cps) * 32;
        const float* A = Aseg[s];
        const int lda = ldA[s];
        {
            const size_t so = (size_t)w0off + (size_t)s * 65536 +
                              (size_t)(kk + sb_k) * ldw + bn + sb_n0;
            const uint32_t o = base + (uint32_t)(D_BH(buf) + sb_k * BPAD + sb_n0) * 2;
            const uint32_t o2 = base + (uint32_t)(D_BL(buf) + sb_k * BPAD + sb_n0) * 2;
            cp16(o, g_wsh + so);
            cp16(o + 16, g_wsh + so + 8);
            cp16(o2, g_wsl + so);
            cp16(o2 + 16, g_wsl + so + 8);
        }
        {
            int gr = bm + sa_r; gr = (gr < M) ? gr : (M - 1);
            const float4* src = (const float4*)(A + (size_t)gr * lda + kk + sa_k0);
            __nv_bfloat16* Ah = dsm + D_AH(buf);
            __nv_bfloat16* Al = dsm + D_AL(buf);
#pragma unroll
            for (int q = 0; q < 4; q++) {
                const float4 v = src[q];
                __nv_bfloat16 h0, l0, h1, l1, h2, l2, h3, l3;
                split_bf16(v.x, h0, l0); split_bf16(v.y, h1, l1);
                split_bf16(v.z, h2, l2); split_bf16(v.w, h3, l3);
                const int o = sa_r * APAD + sa_k0 + q * 4;
                *(uint2*)&Ah[o] = make_uint2(bfpack(h0, h1), bfpack(h2, h3));
                *(uint2*)&Al[o] = make_uint2(bfpack(l0, l1), bfpack(l2, l3));
            }
        }
    };

    stage(0, 0);
    CP_COMMIT();
    CP_WAIT0();
    __syncthreads();

    for (int ch = 0; ch < nchunks; ch++) {
        const int cur = ch & 1;
        if (ch + 1 < nchunks) {
            stage(ch + 1, cur ^ 1);
            CP_COMMIT();
        }

        const uint32_t AhB = base + D_AH(cur) * 2;
        const uint32_t AlB = base + D_AL(cur) * 2;
        const uint32_t BhB = base + D_BH(cur) * 2;
        const uint32_t BlB = base + D_BL(cur) * 2;

#pragma unroll
        for (int ks = 0; ks < 32; ks += 16) {
            uint32_t ahi[2][4], alo[2][4];
#pragma unroll
            for (int mi = 0; mi < 2; mi++) {
                const int m = mq * 32 + mi * 16 + a_m;
                const uint32_t off = (uint32_t)(m * APAD + ks + a_k) * 2;
                ldm_x4(ahi[mi], AhB + off);
                ldm_x4(alo[mi], AlB + off);
            }
#pragma unroll
            for (int nip = 0; nip < 4; nip++) {
                uint32_t bh4[4], bl4[4];
                const uint32_t off =
                    (uint32_t)((ks + b_row) * BPAD + nh * 64 + nip * 16 + b_col8) * 2;
                ldm_x4t(bh4, BhB + off);
                ldm_x4t(bl4, BlB + off);
#pragma unroll
                for (int half = 0; half < 2; half++) {
                    const int ni = nip * 2 + half;
#pragma unroll
                    for (int mi = 0; mi < 2; mi++) {
                        mma16816(acc[mi][ni], ahi[mi], bh4 + half * 2);
                        mma16816(acc[mi][ni], ahi[mi], bl4 + half * 2);
                        mma16816(acc[mi][ni], alo[mi], bh4 + half * 2);
                    }
                }
            }
        }
        CP_WAIT0();
        __syncthreads();
    }

    const float inv = rsqrtf(1.0f + 1e-5f);
    const int r0b = bm + mq * 32 + (lane >> 2);
    const int cb = bn + nh * 64 + (lane & 3) * 2;

    float lacc[2][2][2];   // [mi][half][class] — fused logits partials (EPI==1)
#pragma unroll
    for (int mi = 0; mi < 2; mi++)
#pragma unroll
        for (int half = 0; half < 2; half++) {
            lacc[mi][half][0] = 0.f;
            lacc[mi][half][1] = 0.f;
        }

    float* C = (EPI == 2) ? resolve_w(csel, coff) : nullptr;
#pragma unroll
    for (int ni = 0; ni < 8; ni++) {
        const int col = cb + ni * 8;
        float b0 = 0.f, b1 = 0.f, s0 = 1.f, s1 = 1.f, o0 = 0.f, o1 = 0.f;
        float w20 = 0.f, w21 = 0.f, w30 = 0.f, w31 = 0.f;
        if (EPI == 1) {
            b0 = __ldg(bias + col); b1 = __ldg(bias + col + 1);
            s0 = __ldg(bng + col) * inv; s1 = __ldg(bng + col + 1) * inv;
            o0 = __ldg(bnb + col); o1 = __ldg(bnb + col + 1);
            w20 = __ldg(w2 + col * 2);       w21 = __ldg(w2 + col * 2 + 1);
            w30 = __ldg(w2 + (col + 1) * 2); w31 = __ldg(w2 + (col + 1) * 2 + 1);
        }
#pragma unroll
        for (int mi = 0; mi < 2; mi++) {
#pragma unroll
            for (int half = 0; half < 2; half++) {
                const int r = r0b + mi * 16 + half * 8;
                float x0 = acc[mi][ni][half * 2 + 0];
                float x1 = acc[mi][ni][half * 2 + 1];
                if (EPI == 1) {
                    x0 = fmaxf(x0 + b0, 0.f) * s0 + o0;
                    x1 = fmaxf(x1 + b1, 0.f) * s1 + o1;
                    lacc[mi][half][0] += x0 * w20 + x1 * w30;
                    lacc[mi][half][1] += x0 * w21 + x1 * w31;
                } else {
                    x0 = fmaxf(x0, 0.f);
                    x1 = fmaxf(x1, 0.f);
                    if (r < M)
                        *(float2*)(C + (size_t)r * ldc + col) = make_float2(x0, x1);
                }
            }
        }
    }

    if (EPI == 1) {
#pragma unroll
        for (int mi = 0; mi < 2; mi++)
#pragma unroll
            for (int half = 0; half < 2; half++) {
                float v0 = lacc[mi][half][0];
                float v1 = lacc[mi][half][1];
                v0 += __shfl_xor_sync(0xffffffffu, v0, 1);
                v0 += __shfl_xor_sync(0xffffffffu, v0, 2);
                v1 += __shfl_xor_sync(0xffffffffu, v1, 1);
                v1 += __shfl_xor_sync(0xffffffffu, v1, 2);
                const int r = r0b + mi * 16 + half * 8;
                if ((lane & 3) == 0 && r < M) {
                    atomicAdd(outp + 2 * r, v0);
                    atomicAdd(outp + 2 * r + 1, v1);
                }
            }
    }
}

// ================= split-bf16 HMMA fused edge encoder (512 thr, 2 tiles/CTA) =======
#define EAPAD 72
#define EBPAD 136
#define EMPAD 136
#define ETILES (EE / 64)
#define EPAIRS (ETILES / 2)
#define EO_W1H 0
#define EO_W1L 8704
#define EO_W2H 17408
#define EO_W2L 52224
#define EG_SZ  54784
#define EO_XH(g)  (87040 + (g) * EG_SZ)
#define EO_XL(g)  (EO_XH(g) + 9216)
#define EO_MH(g)  (EO_XL(g) + 9216)
#define EO_ML(g)  (EO_MH(g) + 17408)
#define EO_RED(g) (EO_ML(g) + 17408)
#define EO_B1  196608
#define EO_SC  197120
#define EO_OF  197632
#define EO_B2  198144
#define ESMEM  198656

__global__ __launch_bounds__(512)
void edge_hmma_kernel(const float* __restrict__ edgenet,
                      const float* __restrict__ b1v, const float* __restrict__ gam,
                      const float* __restrict__ bet, const float* __restrict__ b2v,
                      float* __restrict__ ew)
{
    extern __shared__ char sm[];
    const int tid = threadIdx.x;
    const int g = tid >> 8;
    const int gt = tid & 255;
    const int wid = gt >> 5, lane = gt & 31;
    const int mq = wid & 3, nh = wid >> 2;
    const float inv = rsqrtf(1.f + 1e-5f);

    __nv_bfloat16* W1h = (__nv_bfloat16*)(sm + EO_W1H);
    __nv_bfloat16* W1l = (__nv_bfloat16*)(sm + EO_W1L);
    __nv_bfloat16* W2h = (__nv_bfloat16*)(sm + EO_W2H);
    __nv_bfloat16* W2l = (__nv_bfloat16*)(sm + EO_W2L);
    __nv_bfloat16* Xh = (__nv_bfloat16*)(sm + EO_XH(g));
    __nv_bfloat16* Xl = (__nv_bfloat16*)(sm + EO_XL(g));
    __nv_bfloat16* Mh = (__nv_bfloat16*)(sm + EO_MH(g));
    __nv_bfloat16* Ml = (__nv_bfloat16*)(sm + EO_ML(g));
    float* red = (float*)(sm + EO_RED(g));
    float* b1s = (float*)(sm + EO_B1);
    float* scs = (float*)(sm + EO_SC);
    float* ofs = (float*)(sm + EO_OF);
    float* b2s = (float*)(sm + EO_B2);

    if (tid < 256) {
        const int r = tid >> 3, c0 = (tid & 7) * 16;
        const size_t so = (size_t)ENW1_OFF + r * 128 + c0;
        const int o = r * EBPAD + c0;
        *(uint4*)&W1h[o] = *(const uint4*)(g_wsh + so);
        *(uint4*)&W1h[o + 8] = *(const uint4*)(g_wsh + so + 8);
        *(uint4*)&W1l[o] = *(const uint4*)(g_wsl + so);
        *(uint4*)&W1l[o + 8] = *(const uint4*)(g_wsl + so + 8);
    }
    {
        const int r = tid >> 2, c0 = (tid & 3) * 32;
        const size_t so = (size_t)ENW2_OFF + r * 128 + c0;
#pragma unroll
        for (int q = 0; q < 4; q++) {
            *(uint4*)&W2h[r * EBPAD + c0 + q * 8] = *(const uint4*)(g_wsh + so + q * 8);
            *(uint4*)&W2l[r * EBPAD + c0 + q * 8] = *(const uint4*)(g_wsl + so + q * 8);
        }
    }
    if (tid < 128) {
        b1s[tid] = b1v[tid];
        scs[tid] = gam[tid] * inv;
        ofs[tid] = bet[tid];
        b2s[tid] = b2v[tid];
    }
    __syncthreads();

    const uint32_t XhB = smem_u32(Xh), XlB = smem_u32(Xl);
    const uint32_t W1hB = smem_u32(W1h), W1lB = smem_u32(W1l);
    const uint32_t W2hB = smem_u32(W2h), W2lB = smem_u32(W2l);
    const uint32_t MhB = smem_u32(Mh), MlB = smem_u32(Ml);

    const int a_m = lane & 15, a_k = (lane >> 4) << 3;
    const int b_row = lane & 15, b_col8 = (lane >> 4) << 3;
    const int rr = lane >> 2;
    const int cb = nh * 64 + (lane & 3) * 2;
    const int bid = g + 1;

    for (int pair = blockIdx.x; pair < EPAIRS; pair += gridDim.x) {
        const int t = pair * 2 + g;
        {
            const int r = gt >> 2, c0 = (gt & 3) * 16;
            const float4* src = (const float4*)(edgenet + (size_t)(t * 64 + r) * 64 + c0);
#pragma unroll
            for (int q = 0; q < 4; q++) {
                const float4 v = src[q];
                __nv_bfloat16 h0, l0, h1, l1, h2, l2, h3, l3;
                split_bf16(v.x, h0, l0); split_bf16(v.y, h1, l1);
                split_bf16(v.z, h2, l2); split_bf16(v.w, h3, l3);
                const int o = r * EAPAD + c0 + q * 4;
                *(uint2*)&Xh[o] = make_uint2(bfpack(h0, h1), bfpack(h2, h3));
                *(uint2*)&Xl[o] = make_uint2(bfpack(l0, l1), bfpack(l2, l3));
            }
        }
        barg(bid, 256);

        float hacc[2][8][4];
#pragma unroll
        for (int half = 0; half < 2; half++) {
            float macc[8][4];
#pragma unroll
            for (int ni = 0; ni < 8; ni++)
#pragma unroll
                for (int q = 0; q < 4; q++) macc[ni][q] = 0.f;
#pragma unroll
            for (int ks = 0; ks < 32; ks += 16) {
                uint32_t ah[4], al[4];
                const uint32_t aoff =
                    (uint32_t)((mq * 16 + a_m) * EAPAD + half * 32 + ks + a_k) * 2;
                ldm_x4(ah, XhB + aoff);
                ldm_x4(al, XlB + aoff);
#pragma unroll
                for (int nip = 0; nip < 4; nip++) {
                    uint32_t bh4[4], bl4[4];
                    const uint32_t boff =
                        (uint32_t)((ks + b_row) * EBPAD + nh * 64 + nip * 16 + b_col8) * 2;
                    ldm_x4t(bh4, W1hB + boff);
                    ldm_x4t(bl4, W1lB + boff);
#pragma unroll
                    for (int hh = 0; hh < 2; hh++) {
                        const int ni = nip * 2 + hh;
                        mma16816(macc[ni], ah, bh4 + hh * 2);
                        mma16816(macc[ni], ah, bl4 + hh * 2);
                        mma16816(macc[ni], al, bh4 + hh * 2);
                    }
                }
            }
            barg(bid, 256);
            {
                const int r0 = mq * 16 + rr;
#pragma unroll
                for (int ni = 0; ni < 8; ni++) {
                    const int col = cb + ni * 8;
                    const float s0 = scs[col], s1 = scs[col + 1];
                    const float bb0 = b1s[col], bb1 = b1s[col + 1];
                    const float o0 = ofs[col], o1 = ofs[col + 1];
                    const float v00 = fmaxf(macc[ni][0] + bb0, 0.f) * s0 + o0;
                    const float v01 = fmaxf(macc[ni][1] + bb1, 0.f) * s1 + o1;
                    const float v10 = fmaxf(macc[ni][2] + bb0, 0.f) * s0 + o0;
                    const float v11 = fmaxf(macc[ni][3] + bb1, 0.f) * s1 + o1;
                    __nv_bfloat16 h0, l0, h1, l1;
                    split_bf16(v00, h0, l0); split_bf16(v01, h1, l1);
                    *(uint32_t*)&Mh[r0 * EMPAD + col] = bfpack(h0, h1);
                    *(uint32_t*)&Ml[r0 * EMPAD + col] = bfpack(l0, l1);
                    split_bf16(v10, h0, l0); split_bf16(v11, h1, l1);
                    *(uint32_t*)&Mh[(r0 + 8) * EMPAD + col] = bfpack(h0, h1);
                    *(uint32_t*)&Ml[(r0 + 8) * EMPAD + col] = bfpack(l0, l1);
                }
            }
            barg(bid, 256);
#pragma unroll
            for (int ni = 0; ni < 8; ni++)
#pragma unroll
                for (int q = 0; q < 4; q++) hacc[half][ni][q] = 0.f;
#pragma unroll
            for (int ks = 0; ks < 128; ks += 16) {
                uint32_t ah[4], al[4];
                const uint32_t aoff = (uint32_t)((mq * 16 + a_m) * EMPAD + ks + a_k) * 2;
                ldm_x4(ah, MhB + aoff);
                ldm_x4(al, MlB + aoff);
#pragma unroll
                for (int nip = 0; nip < 4; nip++) {
                    uint32_t bh4[4], bl4[4];
                    const uint32_t boff =
                        (uint32_t)((ks + b_row) * EBPAD + nh * 64 + nip * 16 + b_col8) * 2;
                    ldm_x4t(bh4, W2hB + boff);
                    ldm_x4t(bl4, W2lB + boff);
#pragma unroll
                    for (int hh = 0; hh < 2; hh++) {
                        const int ni = nip * 2 + hh;
                        mma16816(hacc[half][ni], ah, bh4 + hh * 2);
                        mma16816(hacc[half][ni], ah, bl4 + hh * 2);
                        mma16816(hacc[half][ni], al, bh4 + hh * 2);
                    }
                }
            }
        }

        float p11a = 0.f, p22a = 0.f, p12a = 0.f;
        float p11b = 0.f, p22b = 0.f, p12b = 0.f;
#pragma unroll
        for (int ni = 0; ni < 8; ni++) {
            const int col = cb + ni * 8;
#pragma unroll
            for (int q = 0; q < 2; q++) {
                const float bb = b2s[col + q];
                const float h0a = hacc[0][ni][q] + bb;
                const float h1a = hacc[1][ni][q] + bb;
                const float h0b = hacc[0][ni][q + 2] + bb;
                const float h1b = hacc[1][ni][q + 2] + bb;
                p11a += h0a * h0a; p22a += h1a * h1a; p12a += h0a * h1a;
                p11b += h0b * h0b; p22b += h1b * h1b; p12b += h0b * h1b;
            }
        }
#pragma unroll
        for (int m = 1; m <= 2; m <<= 1) {
            p11a += __shfl_xor_sync(0xffffffffu, p11a, m);
            p22a += __shfl_xor_sync(0xffffffffu, p22a, m);
            p12a += __shfl_xor_sync(0xffffffffu, p12a, m);
            p11b += __shfl_xor_sync(0xffffffffu, p11b, m);
            p22b += __shfl_xor_sync(0xffffffffu, p22b, m);
            p12b += __shfl_xor_sync(0xffffffffu, p12b, m);
        }
        if ((lane & 3) == 0) {
            const int r0 = mq * 16 + rr;
            red[0 * 128 + nh * 64 + r0] = p11a;
            red[1 * 128 + nh * 64 + r0] = p22a;
            red[2 * 128 + nh * 64 + r0] = p12a;
            red[0 * 128 + nh * 64 + r0 + 8] = p11b;
            red[1 * 128 + nh * 64 + r0 + 8] = p22b;
            red[2 * 128 + nh * 64 + r0 + 8] = p12b;
        }
        barg(bid, 256);
        if (gt < 64) {
            const float s11 = red[0 * 128 + gt] + red[0 * 128 + 64 + gt];
            const float s22 = red[1 * 128 + gt] + red[1 * 128 + 64 + gt];
            const float s12 = red[2 * 128 + gt] + red[2 * 128 + 64 + gt];
            const float n1 = fmaxf(sqrtf(s11), 1e-8f);
            const float n2 = fmaxf(sqrtf(s22), 1e-8f);
            ew[t * 64 + gt] = (s12 / (n1 * n2) + 1.f) * 0.5f;
        }
        barg(bid, 256);
    }
}

// ---------------- CSR build ----------------
__global__ void degcnt_kernel(const void* __restrict__ ei, const float* __restrict__ ew)
{
    const int e = blockIdx.x * blockDim.x + threadIdx.x;
    if (e < EE) {
        const int row = idx_at(ei, e);
        const int col = idx_at(ei, e + EE);
        atomicAdd(&g_deg[row], ew[e]);
        atomicAdd(&g_cnt[col], 1);
    }
}

__global__ void dis_kernel()
{
    const int n = blockIdx.x * blockDim.x + threadIdx.x;
    if (n < NN) {
        const float d = g_deg[n];
        g_dis[n] = (d > 0.f) ? rsqrtf(fmaxf(d, 1e-30f)) : 0.f;
    }
}

__global__ void scan_kernel()
{
    __shared__ int sm[1024];
    __shared__ int carry;
    const int tid = threadIdx.x;
    if (tid == 0) carry = 0;
    __syncthreads();
    for (int base = 0; base < NN; base += 1024) {
        const int idx = base + tid;
        const int v = (idx < NN) ? g_cnt[idx] : 0;
        sm[tid] = v;
        __syncthreads();
        for (int off = 1; off < 1024; off <<= 1) {
            const int t = (tid >= off) ? sm[tid - off] : 0;
            __syncthreads();
            sm[tid] += t;
            __syncthreads();
        }
        const int c = carry;
        if (idx < NN) g_starts[idx] = c + sm[tid] - v;
        const int tot = sm[1023];
        __syncthreads();
        if (tid == 0) carry = c + tot;
        __syncthreads();
    }
    if (tid == 0) g_starts[NN] = carry;
}

__global__ void fill_kernel(const void* __restrict__ ei, const float* __restrict__ ew)
{
    const int e = blockIdx.x * blockDim.x + threadIdx.x;
    if (e < EE) {
        const int row = idx_at(ei, e);
        const int col = idx_at(ei, e + EE);
        const int p = g_starts[col] + atomicAdd(&g_cur[col], 1);
        g_srcA[p] = row;
        g_wA[p] = -g_dis[row] * ew[e] * g_dis[col];
    }
}

// ---------------- sparse propagation (fp32, R14 2-edge form) ----------------
__global__ __launch_bounds__(64)
void prop_kernel(int xsel, const float* __restrict__ xext, int xoff, int ldx,
                 int x0sel, const float* __restrict__ x0ext, int x0off, int ldx0,
                 int osel, int mode)
{
    const float* X  = resolve_c(xsel, xext, xoff);
    const float* X0 = (mode ? resolve_c(x0sel, x0ext, x0off) : nullptr);
    float* out = resolve_w(osel, 0);
    const int n = blockIdx.x;
    const int t = threadIdx.x;
    const int s0 = g_starts[n];
    const int s1 = g_starts[n + 1];
    float4 a = make_float4(0, 0, 0, 0);
    float4 b = make_float4(0, 0, 0, 0);
    int i = s0;
    for (; i + 1 < s1; i += 2) {
        const float w0 = g_wA[i];
        const float w1 = g_wA[i + 1];
        const int r0 = g_srcA[i];
        const int r1 = g_srcA[i + 1];
        const float4 x0 = *(const float4*)(X + (size_t)r0 * ldx + (t << 2));
        const float4 x1 = *(const float4*)(X + (size_t)r1 * ldx + (t << 2));
        a.x += w0 * x0.x; a.y += w0 * x0.y; a.z += w0 * x0.z; a.w += w0 * x0.w;
        b.x += w1 * x1.x; b.y += w1 * x1.y; b.z += w1 * x1.z; b.w += w1 * x1.w;
    }
    if (i < s1) {
        const float w0 = g_wA[i];
        const int r0 = g_srcA[i];
        const float4 x0 = *(const float4*)(X + (size_t)r0 * ldx + (t << 2));
        a.x += w0 * x0.x; a.y += w0 * x0.y; a.z += w0 * x0.z; a.w += w0 * x0.w;
    }
    float4 r = make_float4(a.x + b.x, a.y + b.y, a.z + b.z, a.w + b.w);
    if (mode) {
        const float4 xv = *(const float4*)(X0 + (size_t)n * ldx0 + (t << 2));
        r.x = 2.f * r.x - xv.x;
        r.y = 2.f * r.y - xv.y;
        r.z = 2.f * r.z - xv.z;
        r.w = 2.f * r.w - xv.w;
    }
    *(float4*)(out + (size_t)n * 256 + (t << 2)) = r;
}

// ---------------- launch ----------------
extern "C" void kernel_launch(void* const* d_in, const int* in_sizes, int n_in,
                              void* d_out, int out_size)
{
    (void)in_sizes; (void)n_in; (void)out_size;
    const float* features = (const float*)d_in[0];
    const void*  ei       = d_in[1];
    const float* edgenet  = (const float*)d_in[2];
    const float* cheb     = (const float*)d_in[3];
    const float* en_w1    = (const float*)d_in[4];
    const float* en_b1    = (const float*)d_in[5];
    const float* en_g1    = (const float*)d_in[6];
    const float* en_be1   = (const float*)d_in[7];
    const float* en_w2    = (const float*)d_in[8];
    const float* en_b2    = (const float*)d_in[9];
    const float* cls_w1   = (const float*)d_in[10];
    const float* cls_b1   = (const float*)d_in[11];
    const float* cls_g    = (const float*)d_in[12];
    const float* cls_b    = (const float*)d_in[13];
    const float* cls_w2   = (const float*)d_in[14];
    const float* cls_b2   = (const float*)d_in[15];
    float* out = (float*)d_out;
    float* ew  = out + NN * 2;

    cudaFuncSetAttribute(edge_hmma_kernel,
                         cudaFuncAttributeMaxDynamicSharedMemorySize, ESMEM);
    cudaFuncSetAttribute(hmma_kernel<1>,
                         cudaFuncAttributeMaxDynamicSharedMemorySize, HSMEM);
    cudaFuncSetAttribute(hmma_kernel<2>,
                         cudaFuncAttributeMaxDynamicSharedMemorySize, HSMEM);

    detect_kernel<<<1, 32>>>(ei);
    zero_kernel<<<(NN + 255) / 256, 256>>>(out, cls_b2);
    split_weights_kernel<<<(WTOTAL + 255) / 256, 256>>>(cheb, cls_w1, en_w1, en_w2);

    edge_hmma_kernel<<<148, 512, ESMEM>>>(edgenet, en_b1, en_g1, en_be1, en_b2, ew);

    degcnt_kernel<<<(EE + 255) / 256, 256>>>(ei, ew);
    dis_kernel<<<(NN + 255) / 256, 256>>>();
    scan_kernel<<<1, 1024>>>();
    fill_kernel<<<(EE + 255) / 256, 256>>>(ei, ew);

    const int mtiles = (NN + 127) / 128;
    for (int l = 0; l < 4; l++) {
        const int xsel = (l == 0) ? SEL_EXT : SEL_JK;
        const int xoff = (l == 0) ? 0 : (l - 1) * 256;
        const int ldx  = (l == 0) ? 256 : 1024;
        prop_kernel<<<NN, 64>>>(xsel, features, xoff, ldx,
                                0, nullptr, 0, 0, SEL_T1, 0);
        prop_kernel<<<NN, 64>>>(SEL_T1, nullptr, 0, 256,
                                xsel, features, xoff, ldx, SEL_T2, 1);
        dim3 gC(mtiles, 2);
        hmma_kernel<2><<<gC, 256, HSMEM>>>(
            xsel, features, xoff, ldx,
            (l * 3) * 65536, 3, 8, 256,
            SEL_JK, l * 256, 1024, NN,
            nullptr, nullptr, nullptr, nullptr, nullptr);
    }

    dim3 gZ(mtiles, 2);
    hmma_kernel<1><<<gZ, 256, HSMEM>>>(
        SEL_JK, nullptr, 0, 1024,
        CLS_OFF, 1, 32, 256,
        SEL_JK, 0, 256, NN,
        cls_b1, cls_g, cls_b, cls_w2, out);
}

// round 17
// speedup vs baseline: 1.0503x; 1.0213x over previous
#include <cuda_runtime.h>
#include <cuda_bf16.h>
#include <math.h>
#include <stdint.h>

#define NN 20000
#define EE 400000

// ---------------- mma.sync / ldmatrix / cp.async helpers ----------------
__device__ __forceinline__ uint32_t smem_u32(const void* p) {
    uint32_t a;
    asm("{ .reg .u64 t; cvta.to.shared.u64 t, %1; cvt.u32.u64 %0, t; }" : "=r"(a) : "l"(p));
    return a;
}
__device__ __forceinline__ void ldm_x4(uint32_t* r, uint32_t addr) {
    asm volatile("ldmatrix.sync.aligned.m8n8.x4.shared.b16 {%0,%1,%2,%3}, [%4];"
                 : "=r"(r[0]), "=r"(r[1]), "=r"(r[2]), "=r"(r[3]) : "r"(addr));
}
__device__ __forceinline__ void ldm_x4t(uint32_t* r, uint32_t addr) {
    asm volatile("ldmatrix.sync.aligned.m8n8.x4.trans.shared.b16 {%0,%1,%2,%3}, [%4];"
                 : "=r"(r[0]), "=r"(r[1]), "=r"(r[2]), "=r"(r[3]) : "r"(addr));
}
__device__ __forceinline__ void mma16816(float* c, const uint32_t* a, const uint32_t* b) {
    asm volatile(
        "mma.sync.aligned.m16n8k16.row.col.f32.bf16.bf16.f32 "
        "{%0,%1,%2,%3}, {%4,%5,%6,%7}, {%8,%9}, {%0,%1,%2,%3};"
        : "+f"(c[0]), "+f"(c[1]), "+f"(c[2]), "+f"(c[3])
        : "r"(a[0]), "r"(a[1]), "r"(a[2]), "r"(a[3]), "r"(b[0]), "r"(b[1]));
}
__device__ __forceinline__ void cp16(uint32_t smem, const void* gmem) {
    asm volatile("cp.async.ca.shared.global [%0], [%1], 16;"
                 :: "r"(smem), "l"(gmem) : "memory");
}
#define CP_COMMIT() asm volatile("cp.async.commit_group;" ::: "memory")
#define CP_WAIT0()  asm volatile("cp.async.wait_group 0;" ::: "memory")
__device__ __forceinline__ void barg(int id, int cnt) {
    asm volatile("bar.sync %0, %1;" :: "r"(id), "r"(cnt) : "memory");
}
__device__ __forceinline__ void split_bf16(float v, __nv_bfloat16& h, __nv_bfloat16& l) {
    h = __float2bfloat16(v);
    l = __float2bfloat16(v - __bfloat162float(h));
}
__device__ __forceinline__ uint32_t bfpack(__nv_bfloat16 a, __nv_bfloat16 b) {
    return ((uint32_t)*(uint16_t*)&b << 16) | (uint32_t)*(uint16_t*)&a;
}

// ---------------- scratch ----------------
#define CLS_OFF  786432
#define ENW1_OFF 1048576
#define ENW2_OFF 1052672
#define WTOTAL   1069056

__device__ float g_t1[(size_t)NN * 256];
__device__ float g_t2[(size_t)NN * 256];
__device__ float g_jk[(size_t)NN * 1024];
__device__ float g_deg[NN];
__device__ float g_dis[NN];
__device__ int   g_cnt[NN];
__device__ int   g_cur[NN];
__device__ int   g_starts[NN + 1];
__device__ int   g_srcA[EE];
__device__ float g_wA[EE];
__device__ int   g_is64;
__device__ __nv_bfloat16 g_wsh[WTOTAL];
__device__ __nv_bfloat16 g_wsl[WTOTAL];

#define SEL_EXT 0
#define SEL_T1  1
#define SEL_T2  2
#define SEL_JK  3

__device__ __forceinline__ const float* resolve_c(int sel, const float* ext, int off) {
    const float* p;
    switch (sel) {
        case SEL_T1: p = g_t1; break;
        case SEL_T2: p = g_t2; break;
        case SEL_JK: p = g_jk; break;
        default:     p = ext;  break;
    }
    return p + off;
}
__device__ __forceinline__ float* resolve_w(int sel, int off) {
    float* p;
    switch (sel) {
        case SEL_T1: p = g_t1; break;
        case SEL_T2: p = g_t2; break;
        default:     p = g_jk; break;
    }
    return p + off;
}
__device__ __forceinline__ int idx_at(const void* ei, int i) {
    if (g_is64) return (int)((const long long*)ei)[i];
    return ((const int*)ei)[i];
}

__global__ void detect_kernel(const void* ei) {
    if (threadIdx.x == 0 && blockIdx.x == 0) {
        const long long* p = (const long long*)ei;
        int ok = 1;
        for (int i = 0; i < 64; i++) {
            long long v = p[i];
            if (v < 0 || v >= NN) ok = 0;
        }
        g_is64 = ok;
    }
}

__global__ void zero_kernel(float* __restrict__ outp, const float* __restrict__ b2)
{
    int n = blockIdx.x * blockDim.x + threadIdx.x;
    if (n < NN) {
        g_deg[n] = 0.f; g_cnt[n] = 0; g_cur[n] = 0;
        outp[2 * n] = b2[0];
        outp[2 * n + 1] = b2[1];
    }
}

// ---------------- pre-split all weights to bf16 hi/lo ----------------
__global__ void split_weights_kernel(const float* __restrict__ cheb,
                                     const float* __restrict__ cls_w1,
                                     const float* __restrict__ en_w1,
                                     const float* __restrict__ en_w2)
{
    const int i = blockIdx.x * blockDim.x + threadIdx.x;
    if (i >= WTOTAL) return;
    float v;
    if (i < CLS_OFF) v = cheb[i];
    else if (i < ENW1_OFF) v = cls_w1[i - CLS_OFF];
    else if (i < ENW2_OFF) v = en_w1[i - ENW1_OFF];
    else v = en_w2[i - ENW2_OFF];
    __nv_bfloat16 h, l;
    split_bf16(v, h, l);
    g_wsh[i] = h;
    g_wsl[i] = l;
}

// ================= split-bf16 HMMA GEMM for node-side matrices ==========
#define APAD 40
#define BPAD 136
#define HA_SZ (128 * APAD)
#define HB_SZ (32 * BPAD)
#define D_AH(b) ((b) * HA_SZ)
#define D_AL(b) (2 * HA_SZ + (b) * HA_SZ)
#define D_BH(b) (4 * HA_SZ + (b) * HB_SZ)
#define D_BL(b) (4 * HA_SZ + 2 * HB_SZ + (b) * HB_SZ)
#define HSMEM ((4 * HA_SZ + 4 * HB_SZ) * 2)   // 75776 bytes

template <int EPI>
__global__ __launch_bounds__(256, 2)
void hmma_kernel(int a0sel, const float* __restrict__ a0ext, int a0off, int lda0,
                 int w0off, int nseg, int cps, int ldw,
                 int csel, int coff, int ldc, int M,
                 const float* __restrict__ bias,
                 const float* __restrict__ bng, const float* __restrict__ bnb,
                 const float* __restrict__ w2, float* __restrict__ outp)
{
    extern __shared__ __nv_bfloat16 dsm[];

    const int tid = threadIdx.x;
    const int wid = tid >> 5;
    const int lane = tid & 31;
    const int bm = blockIdx.x * 128;
    const int bn = blockIdx.y * 128;
    const int mq = wid & 3;
    const int nh = wid >> 2;

    float acc[2][8][4];
#pragma unroll
    for (int mi = 0; mi < 2; mi++)
#pragma unroll
        for (int ni = 0; ni < 8; ni++)
#pragma unroll
            for (int q = 0; q < 4; q++) acc[mi][ni][q] = 0.f;

    const float* Aseg[3] = { resolve_c(a0sel, a0ext, a0off), g_t1, g_t2 };
    const int ldA[3] = { lda0, 256, 256 };

    const uint32_t base = smem_u32(dsm);
    const int a_m = (lane & 15);
    const int a_k = ((lane >> 4) << 3);
    const int b_row = (lane & 15);
    const int b_col8 = ((lane >> 4) << 3);

    const int sa_r = tid >> 1;
    const int sa_k0 = (tid & 1) * 16;
    const int sb_k = tid >> 3;
    const int sb_n0 = (tid & 7) * 16;

    const int nchunks = nseg * cps;

    auto stage = [&](int ch, int buf) {
        const int s = ch / cps;
        const int kk = (ch % cps) * 32;
        const float* A = Aseg[s];
        const int lda = ldA[s];
        {
            const size_t so = (size_t)w0off + (size_t)s * 65536 +
                              (size_t)(kk + sb_k) * ldw + bn + sb_n0;
            const uint32_t o = base + (uint32_t)(D_BH(buf) + sb_k * BPAD + sb_n0) * 2;
            const uint32_t o2 = base + (uint32_t)(D_BL(buf) + sb_k * BPAD + sb_n0) * 2;
            cp16(o, g_wsh + so);
            cp16(o + 16, g_wsh + so + 8);
            cp16(o2, g_wsl + so);
            cp16(o2 + 16, g_wsl + so + 8);
        }
        {
            int gr = bm + sa_r; gr = (gr < M) ? gr : (M - 1);
            const float4* src = (const float4*)(A + (size_t)gr * lda + kk + sa_k0);
            __nv_bfloat16* Ah = dsm + D_AH(buf);
            __nv_bfloat16* Al = dsm + D_AL(buf);
#pragma unroll
            for (int q = 0; q < 4; q++) {
                const float4 v = src[q];
                __nv_bfloat16 h0, l0, h1, l1, h2, l2, h3, l3;
                split_bf16(v.x, h0, l0); split_bf16(v.y, h1, l1);
                split_bf16(v.z, h2, l2); split_bf16(v.w, h3, l3);
                const int o = sa_r * APAD + sa_k0 + q * 4;
                *(uint2*)&Ah[o] = make_uint2(bfpack(h0, h1), bfpack(h2, h3));
                *(uint2*)&Al[o] = make_uint2(bfpack(l0, l1), bfpack(l2, l3));
            }
        }
    };

    stage(0, 0);
    CP_COMMIT();
    CP_WAIT0();
    __syncthreads();

    for (int ch = 0; ch < nchunks; ch++) {
        const int cur = ch & 1;
        if (ch + 1 < nchunks) {
            stage(ch + 1, cur ^ 1);
            CP_COMMIT();
        }

        const uint32_t AhB = base + D_AH(cur) * 2;
        const uint32_t AlB = base + D_AL(cur) * 2;
        const uint32_t BhB = base + D_BH(cur) * 2;
        const uint32_t BlB = base + D_BL(cur) * 2;

#pragma unroll
        for (int ks = 0; ks < 32; ks += 16) {
            uint32_t ahi[2][4], alo[2][4];
#pragma unroll
            for (int mi = 0; mi < 2; mi++) {
                const int m = mq * 32 + mi * 16 + a_m;
                const uint32_t off = (uint32_t)(m * APAD + ks + a_k) * 2;
                ldm_x4(ahi[mi], AhB + off);
                ldm_x4(alo[mi], AlB + off);
            }
#pragma unroll
            for (int nip = 0; nip < 4; nip++) {
                uint32_t bh4[4], bl4[4];
                const uint32_t off =
                    (uint32_t)((ks + b_row) * BPAD + nh * 64 + nip * 16 + b_col8) * 2;
                ldm_x4t(bh4, BhB + off);
                ldm_x4t(bl4, BlB + off);
#pragma unroll
                for (int half = 0; half < 2; half++) {
                    const int ni = nip * 2 + half;
#pragma unroll
                    for (int mi = 0; mi < 2; mi++) {
                        mma16816(acc[mi][ni], ahi[mi], bh4 + half * 2);
                        mma16816(acc[mi][ni], ahi[mi], bl4 + half * 2);
                        mma16816(acc[mi][ni], alo[mi], bh4 + half * 2);
                    }
                }
            }
        }
        CP_WAIT0();
        __syncthreads();
    }

    const float inv = rsqrtf(1.0f + 1e-5f);
    const int r0b = bm + mq * 32 + (lane >> 2);
    const int cb = bn + nh * 64 + (lane & 3) * 2;

    float lacc[2][2][2];
#pragma unroll
    for (int mi = 0; mi < 2; mi++)
#pragma unroll
        for (int half = 0; half < 2; half++) {
            lacc[mi][half][0] = 0.f;
            lacc[mi][half][1] = 0.f;
        }

    float* C = (EPI == 2) ? resolve_w(csel, coff) : nullptr;
#pragma unroll
    for (int ni = 0; ni < 8; ni++) {
        const int col = cb + ni * 8;
        float b0 = 0.f, b1 = 0.f, s0 = 1.f, s1 = 1.f, o0 = 0.f, o1 = 0.f;
        float w20 = 0.f, w21 = 0.f, w30 = 0.f, w31 = 0.f;
        if (EPI == 1) {
            b0 = __ldg(bias + col); b1 = __ldg(bias + col + 1);
            s0 = __ldg(bng + col) * inv; s1 = __ldg(bng + col + 1) * inv;
            o0 = __ldg(bnb + col); o1 = __ldg(bnb + col + 1);
            w20 = __ldg(w2 + col * 2);       w21 = __ldg(w2 + col * 2 + 1);
            w30 = __ldg(w2 + (col + 1) * 2); w31 = __ldg(w2 + (col + 1) * 2 + 1);
        }
#pragma unroll
        for (int mi = 0; mi < 2; mi++) {
#pragma unroll
            for (int half = 0; half < 2; half++) {
                const int r = r0b + mi * 16 + half * 8;
                float x0 = acc[mi][ni][half * 2 + 0];
                float x1 = acc[mi][ni][half * 2 + 1];
                if (EPI == 1) {
                    x0 = fmaxf(x0 + b0, 0.f) * s0 + o0;
                    x1 = fmaxf(x1 + b1, 0.f) * s1 + o1;
                    lacc[mi][half][0] += x0 * w20 + x1 * w30;
                    lacc[mi][half][1] += x0 * w21 + x1 * w31;
                } else {
                    x0 = fmaxf(x0, 0.f);
                    x1 = fmaxf(x1, 0.f);
                    if (r < M)
                        *(float2*)(C + (size_t)r * ldc + col) = make_float2(x0, x1);
                }
            }
        }
    }

    if (EPI == 1) {
#pragma unroll
        for (int mi = 0; mi < 2; mi++)
#pragma unroll
            for (int half = 0; half < 2; half++) {
                float v0 = lacc[mi][half][0];
                float v1 = lacc[mi][half][1];
                v0 += __shfl_xor_sync(0xffffffffu, v0, 1);
                v0 += __shfl_xor_sync(0xffffffffu, v0, 2);
                v1 += __shfl_xor_sync(0xffffffffu, v1, 1);
                v1 += __shfl_xor_sync(0xffffffffu, v1, 2);
                const int r = r0b + mi * 16 + half * 8;
                if ((lane & 3) == 0 && r < M) {
                    atomicAdd(outp + 2 * r, v0);
                    atomicAdd(outp + 2 * r + 1, v1);
                }
            }
    }
}

// ================= split-bf16 HMMA fused edge encoder ==================
// 512 thr, 2 tiles/CTA; warp tile m32 x n32 (2 row-halves x 4 col-quarters).
#define EAPAD 72
#define EBPAD 136
#define EMPAD 136
#define ETILES (EE / 64)
#define EPAIRS (ETILES / 2)
#define EO_W1H 0
#define EO_W1L 8704
#define EO_W2H 17408
#define EO_W2L 52224
#define EG_SZ  56320
#define EO_XH(g)  (87040 + (g) * EG_SZ)
#define EO_XL(g)  (EO_XH(g) + 9216)
#define EO_MH(g)  (EO_XL(g) + 9216)
#define EO_ML(g)  (EO_MH(g) + 17408)
#define EO_RED(g) (EO_ML(g) + 17408)
#define EO_B1  199680
#define EO_SC  200192
#define EO_OF  200704
#define EO_B2  201216
#define ESMEM  201728

__global__ __launch_bounds__(512)
void edge_hmma_kernel(const float* __restrict__ edgenet,
                      const float* __restrict__ b1v, const float* __restrict__ gam,
                      const float* __restrict__ bet, const float* __restrict__ b2v,
                      float* __restrict__ ew)
{
    extern __shared__ char sm[];
    const int tid = threadIdx.x;
    const int g = tid >> 8;
    const int gt = tid & 255;
    const int wid = gt >> 5, lane = gt & 31;
    const int mq = wid & 1;     // 32-row half
    const int nh = wid >> 1;    // 32-col quarter
    const float inv = rsqrtf(1.f + 1e-5f);

    __nv_bfloat16* W1h = (__nv_bfloat16*)(sm + EO_W1H);
    __nv_bfloat16* W1l = (__nv_bfloat16*)(sm + EO_W1L);
    __nv_bfloat16* W2h = (__nv_bfloat16*)(sm + EO_W2H);
    __nv_bfloat16* W2l = (__nv_bfloat16*)(sm + EO_W2L);
    __nv_bfloat16* Xh = (__nv_bfloat16*)(sm + EO_XH(g));
    __nv_bfloat16* Xl = (__nv_bfloat16*)(sm + EO_XL(g));
    __nv_bfloat16* Mh = (__nv_bfloat16*)(sm + EO_MH(g));
    __nv_bfloat16* Ml = (__nv_bfloat16*)(sm + EO_ML(g));
    float* red = (float*)(sm + EO_RED(g));   // [3][4 quarters][64 rows]
    float* b1s = (float*)(sm + EO_B1);
    float* scs = (float*)(sm + EO_SC);
    float* ofs = (float*)(sm + EO_OF);
    float* b2s = (float*)(sm + EO_B2);

    if (tid < 256) {
        const int r = tid >> 3, c0 = (tid & 7) * 16;
        const size_t so = (size_t)ENW1_OFF + r * 128 + c0;
        const int o = r * EBPAD + c0;
        *(uint4*)&W1h[o] = *(const uint4*)(g_wsh + so);
        *(uint4*)&W1h[o + 8] = *(const uint4*)(g_wsh + so + 8);
        *(uint4*)&W1l[o] = *(const uint4*)(g_wsl + so);
        *(uint4*)&W1l[o + 8] = *(const uint4*)(g_wsl + so + 8);
    }
    {
        const int r = tid >> 2, c0 = (tid & 3) * 32;
        const size_t so = (size_t)ENW2_OFF + r * 128 + c0;
#pragma unroll
        for (int q = 0; q < 4; q++) {
            *(uint4*)&W2h[r * EBPAD + c0 + q * 8] = *(const uint4*)(g_wsh + so + q * 8);
            *(uint4*)&W2l[r * EBPAD + c0 + q * 8] = *(const uint4*)(g_wsl + so + q * 8);
        }
    }
    if (tid < 128) {
        b1s[tid] = b1v[tid];
        scs[tid] = gam[tid] * inv;
        ofs[tid] = bet[tid];
        b2s[tid] = b2v[tid];
    }
    __syncthreads();

    const uint32_t XhB = smem_u32(Xh), XlB = smem_u32(Xl);
    const uint32_t W1hB = smem_u32(W1h), W1lB = smem_u32(W1l);
    const uint32_t W2hB = smem_u32(W2h), W2lB = smem_u32(W2l);
    const uint32_t MhB = smem_u32(Mh), MlB = smem_u32(Ml);

    const int a_m = lane & 15, a_k = (lane >> 4) << 3;
    const int b_row = lane & 15, b_col8 = (lane >> 4) << 3;
    const int rr = lane >> 2;
    const int cb = nh * 32 + (lane & 3) * 2;
    const int bid = g + 1;

    for (int pair = blockIdx.x; pair < EPAIRS; pair += gridDim.x) {
        const int t = pair * 2 + g;
        {
            const int r = gt >> 2, c0 = (gt & 3) * 16;
            const float4* src = (const float4*)(edgenet + (size_t)(t * 64 + r) * 64 + c0);
#pragma unroll
            for (int q = 0; q < 4; q++) {
                const float4 v = src[q];
                __nv_bfloat16 h0, l0, h1, l1, h2, l2, h3, l3;
                split_bf16(v.x, h0, l0); split_bf16(v.y, h1, l1);
                split_bf16(v.z, h2, l2); split_bf16(v.w, h3, l3);
                const int o = r * EAPAD + c0 + q * 4;
                *(uint2*)&Xh[o] = make_uint2(bfpack(h0, h1), bfpack(h2, h3));
                *(uint2*)&Xl[o] = make_uint2(bfpack(l0, l1), bfpack(l2, l3));
            }
        }
        barg(bid, 256);

        float hacc[2][2][4][4];   // [half][mi][ni][4]
#pragma unroll
        for (int half = 0; half < 2; half++) {
            float macc[2][4][4];  // [mi][ni][4]
#pragma unroll
            for (int mi = 0; mi < 2; mi++)
#pragma unroll
                for (int ni = 0; ni < 4; ni++)
#pragma unroll
                    for (int q = 0; q < 4; q++) macc[mi][ni][q] = 0.f;
            // ---- GEMM1: X[64x32] @ W1[32x128] (warp m32 x n32) ----
#pragma unroll
            for (int ks = 0; ks < 32; ks += 16) {
                uint32_t ah[2][4], al[2][4];
#pragma unroll
                for (int mi = 0; mi < 2; mi++) {
                    const uint32_t aoff =
                        (uint32_t)((mq * 32 + mi * 16 + a_m) * EAPAD +
                                   half * 32 + ks + a_k) * 2;
                    ldm_x4(ah[mi], XhB + aoff);
                    ldm_x4(al[mi], XlB + aoff);
                }
#pragma unroll
                for (int nip = 0; nip < 2; nip++) {
                    uint32_t bh4[4], bl4[4];
                    const uint32_t boff =
                        (uint32_t)((ks + b_row) * EBPAD + nh * 32 + nip * 16 + b_col8) * 2;
                    ldm_x4t(bh4, W1hB + boff);
                    ldm_x4t(bl4, W1lB + boff);
#pragma unroll
                    for (int hh = 0; hh < 2; hh++) {
                        const int ni = nip * 2 + hh;
#pragma unroll
                        for (int mi = 0; mi < 2; mi++) {
                            mma16816(macc[mi][ni], ah[mi], bh4 + hh * 2);
                            mma16816(macc[mi][ni], ah[mi], bl4 + hh * 2);
                            mma16816(macc[mi][ni], al[mi], bh4 + hh * 2);
                        }
                    }
                }
            }
            barg(bid, 256);
            // ---- mid epilogue -> M smem (bf16 hi/lo) ----
#pragma unroll
            for (int mi = 0; mi < 2; mi++) {
                const int r0 = mq * 32 + mi * 16 + rr;
#pragma unroll
                for (int ni = 0; ni < 4; ni++) {
                    const int col = cb + ni * 8;
                    const float s0 = scs[col], s1 = scs[col + 1];
                    const float bb0 = b1s[col], bb1 = b1s[col + 1];
                    const float o0 = ofs[col], o1 = ofs[col + 1];
                    const float v00 = fmaxf(macc[mi][ni][0] + bb0, 0.f) * s0 + o0;
                    const float v01 = fmaxf(macc[mi][ni][1] + bb1, 0.f) * s1 + o1;
                    const float v10 = fmaxf(macc[mi][ni][2] + bb0, 0.f) * s0 + o0;
                    const float v11 = fmaxf(macc[mi][ni][3] + bb1, 0.f) * s1 + o1;
                    __nv_bfloat16 h0, l0, h1, l1;
                    split_bf16(v00, h0, l0); split_bf16(v01, h1, l1);
                    *(uint32_t*)&Mh[r0 * EMPAD + col] = bfpack(h0, h1);
                    *(uint32_t*)&Ml[r0 * EMPAD + col] = bfpack(l0, l1);
                    split_bf16(v10, h0, l0); split_bf16(v11, h1, l1);
                    *(uint32_t*)&Mh[(r0 + 8) * EMPAD + col] = bfpack(h0, h1);
                    *(uint32_t*)&Ml[(r0 + 8) * EMPAD + col] = bfpack(l0, l1);
                }
            }
            barg(bid, 256);
            // ---- GEMM2: M[64x128] @ W2[128x128] (warp m32 x n32) ----
#pragma unroll
            for (int mi = 0; mi < 2; mi++)
#pragma unroll
                for (int ni = 0; ni < 4; ni++)
#pragma unroll
                    for (int q = 0; q < 4; q++) hacc[half][mi][ni][q] = 0.f;
#pragma unroll
            for (int ks = 0; ks < 128; ks += 16) {
                uint32_t ah[2][4], al[2][4];
#pragma unroll
                for (int mi = 0; mi < 2; mi++) {
                    const uint32_t aoff =
                        (uint32_t)((mq * 32 + mi * 16 + a_m) * EMPAD + ks + a_k) * 2;
                    ldm_x4(ah[mi], MhB + aoff);
                    ldm_x4(al[mi], MlB + aoff);
                }
#pragma unroll
                for (int nip = 0; nip < 2; nip++) {
                    uint32_t bh4[4], bl4[4];
                    const uint32_t boff =
                        (uint32_t)((ks + b_row) * EBPAD + nh * 32 + nip * 16 + b_col8) * 2;
                    ldm_x4t(bh4, W2hB + boff);
                    ldm_x4t(bl4, W2lB + boff);
#pragma unroll
                    for (int hh = 0; hh < 2; hh++) {
                        const int ni = nip * 2 + hh;
#pragma unroll
                        for (int mi = 0; mi < 2; mi++) {
                            mma16816(hacc[half][mi][ni], ah[mi], bh4 + hh * 2);
                            mma16816(hacc[half][mi][ni], ah[mi], bl4 + hh * 2);
                            mma16816(hacc[half][mi][ni], al[mi], bh4 + hh * 2);
                        }
                    }
                }
            }
        }

        // ---- cosine: per (mi, row-half) partials over this warp's 32-col quarter ----
        float p11[2][2], p22[2][2], p12[2][2];
#pragma unroll
        for (int mi = 0; mi < 2; mi++)
#pragma unroll
            for (int rh = 0; rh < 2; rh++) {
                p11[mi][rh] = 0.f; p22[mi][rh] = 0.f; p12[mi][rh] = 0.f;
            }
#pragma unroll
        for (int mi = 0; mi < 2; mi++)
#pragma unroll
            for (int ni = 0; ni < 4; ni++) {
                const int col = cb + ni * 8;
#pragma unroll
                for (int rh = 0; rh < 2; rh++)
#pragma unroll
                    for (int qq = 0; qq < 2; qq++) {
                        const float bb = b2s[col + qq];
                        const float h0 = hacc[0][mi][ni][rh * 2 + qq] + bb;
                        const float h1 = hacc[1][mi][ni][rh * 2 + qq] + bb;
                        p11[mi][rh] += h0 * h0;
                        p22[mi][rh] += h1 * h1;
                        p12[mi][rh] += h0 * h1;
                    }
            }
#pragma unroll
        for (int mi = 0; mi < 2; mi++)
#pragma unroll
            for (int rh = 0; rh < 2; rh++) {
#pragma unroll
                for (int m = 1; m <= 2; m <<= 1) {
                    p11[mi][rh] += __shfl_xor_sync(0xffffffffu, p11[mi][rh], m);
                    p22[mi][rh] += __shfl_xor_sync(0xffffffffu, p22[mi][rh], m);
                    p12[mi][rh] += __shfl_xor_sync(0xffffffffu, p12[mi][rh], m);
                }
                if ((lane & 3) == 0) {
                    const int r = mq * 32 + mi * 16 + rh * 8 + rr;
                    red[0 * 256 + nh * 64 + r] = p11[mi][rh];
                    red[1 * 256 + nh * 64 + r] = p22[mi][rh];
                    red[2 * 256 + nh * 64 + r] = p12[mi][rh];
                }
            }
        barg(bid, 256);
        if (gt < 64) {
            const float s11 = (red[0 * 256 + gt] + red[0 * 256 + 64 + gt]) +
                              (red[0 * 256 + 128 + gt] + red[0 * 256 + 192 + gt]);
            const float s22 = (red[1 * 256 + gt] + red[1 * 256 + 64 + gt]) +
                              (red[1 * 256 + 128 + gt] + red[1 * 256 + 192 + gt]);
            const float s12 = (red[2 * 256 + gt] + red[2 * 256 + 64 + gt]) +
                              (red[2 * 256 + 128 + gt] + red[2 * 256 + 192 + gt]);
            const float n1 = fmaxf(sqrtf(s11), 1e-8f);
            const float n2 = fmaxf(sqrtf(s22), 1e-8f);
            ew[t * 64 + gt] = (s12 / (n1 * n2) + 1.f) * 0.5f;
        }
        barg(bid, 256);
    }
}

// ---------------- CSR build ----------------
__global__ void degcnt_kernel(const void* __restrict__ ei, const float* __restrict__ ew)
{
    const int e = blockIdx.x * blockDim.x + threadIdx.x;
    if (e < EE) {
        const int row = idx_at(ei, e);
        const int col = idx_at(ei, e + EE);
        atomicAdd(&g_deg[row], ew[e]);
        atomicAdd(&g_cnt[col], 1);
    }
}

__global__ void dis_kernel()
{
    const int n = blockIdx.x * blockDim.x + threadIdx.x;
    if (n < NN) {
        const float d = g_deg[n];
        g_dis[n] = (d > 0.f) ? rsqrtf(fmaxf(d, 1e-30f)) : 0.f;
    }
}

__global__ void scan_kernel()
{
    __shared__ int sm[1024];
    __shared__ int carry;
    const int tid = threadIdx.x;
    if (tid == 0) carry = 0;
    __syncthreads();
    for (int base = 0; base < NN; base += 1024) {
        const int idx = base + tid;
        const int v = (idx < NN) ? g_cnt[idx] : 0;
        sm[tid] = v;
        __syncthreads();
        for (int off = 1; off < 1024; off <<= 1) {
            const int t = (tid >= off) ? sm[tid - off] : 0;
            __syncthreads();
            sm[tid] += t;
            __syncthreads();
        }
        const int c = carry;
        if (idx < NN) g_starts[idx] = c + sm[tid] - v;
        const int tot = sm[1023];
        __syncthreads();
        if (tid == 0) carry = c + tot;
        __syncthreads();
    }
    if (tid == 0) g_starts[NN] = carry;
}

__global__ void fill_kernel(const void* __restrict__ ei, const float* __restrict__ ew)
{
    const int e = blockIdx.x * blockDim.x + threadIdx.x;
    if (e < EE) {
        const int row = idx_at(ei, e);
        const int col = idx_at(ei, e + EE);
        const int p = g_starts[col] + atomicAdd(&g_cur[col], 1);
        g_srcA[p] = row;
        g_wA[p] = -g_dis[row] * ew[e] * g_dis[col];
    }
}

// ---------------- sparse propagation (fp32, 2-edge form) ----------------
__global__ __launch_bounds__(64)
void prop_kernel(int xsel, const float* __restrict__ xext, int xoff, int ldx,
                 int x0sel, const float* __restrict__ x0ext, int x0off, int ldx0,
                 int osel, int mode)
{
    const float* X  = resolve_c(xsel, xext, xoff);
    const float* X0 = (mode ? resolve_c(x0sel, x0ext, x0off) : nullptr);
    float* out = resolve_w(osel, 0);
    const int n = blockIdx.x;
    const int t = threadIdx.x;
    const int s0 = g_starts[n];
    const int s1 = g_starts[n + 1];
    float4 a = make_float4(0, 0, 0, 0);
    float4 b = make_float4(0, 0, 0, 0);
    int i = s0;
    for (; i + 1 < s1; i += 2) {
        const float w0 = g_wA[i];
        const float w1 = g_wA[i + 1];
        const int r0 = g_srcA[i];
        const int r1 = g_srcA[i + 1];
        const float4 x0 = *(const float4*)(X + (size_t)r0 * ldx + (t << 2));
        const float4 x1 = *(const float4*)(X + (size_t)r1 * ldx + (t << 2));
        a.x += w0 * x0.x; a.y += w0 * x0.y; a.z += w0 * x0.z; a.w += w0 * x0.w;
        b.x += w1 * x1.x; b.y += w1 * x1.y; b.z += w1 * x1.z; b.w += w1 * x1.w;
    }
    if (i < s1) {
        const float w0 = g_wA[i];
        const int r0 = g_srcA[i];
        const float4 x0 = *(const float4*)(X + (size_t)r0 * ldx + (t << 2));
        a.x += w0 * x0.x; a.y += w0 * x0.y; a.z += w0 * x0.z; a.w += w0 * x0.w;
    }
    float4 r = make_float4(a.x + b.x, a.y + b.y, a.z + b.z, a.w + b.w);
    if (mode) {
        const float4 xv = *(const float4*)(X0 + (size_t)n * ldx0 + (t << 2));
        r.x = 2.f * r.x - xv.x;
        r.y = 2.f * r.y - xv.y;
        r.z = 2.f * r.z - xv.z;
        r.w = 2.f * r.w - xv.w;
    }
    *(float4*)(out + (size_t)n * 256 + (t << 2)) = r;
}

// ---------------- launch ----------------
extern "C" void kernel_launch(void* const* d_in, const int* in_sizes, int n_in,
                              void* d_out, int out_size)
{
    (void)in_sizes; (void)n_in; (void)out_size;
    const float* features = (const float*)d_in[0];
    const void*  ei       = d_in[1];
    const float* edgenet  = (const float*)d_in[2];
    const float* cheb     = (const float*)d_in[3];
    const float* en_w1    = (const float*)d_in[4];
    const float* en_b1    = (const float*)d_in[5];
    const float* en_g1    = (const float*)d_in[6];
    const float* en_be1   = (const float*)d_in[7];
    const float* en_w2    = (const float*)d_in[8];
    const float* en_b2    = (const float*)d_in[9];
    const float* cls_w1   = (const float*)d_in[10];
    const float* cls_b1   = (const float*)d_in[11];
    const float* cls_g    = (const float*)d_in[12];
    const float* cls_b    = (const float*)d_in[13];
    const float* cls_w2   = (const float*)d_in[14];
    const float* cls_b2   = (const float*)d_in[15];
    float* out = (float*)d_out;
    float* ew  = out + NN * 2;

    cudaFuncSetAttribute(edge_hmma_kernel,
                         cudaFuncAttributeMaxDynamicSharedMemorySize, ESMEM);
    cudaFuncSetAttribute(hmma_kernel<1>,
                         cudaFuncAttributeMaxDynamicSharedMemorySize, HSMEM);
    cudaFuncSetAttribute(hmma_kernel<2>,
                         cudaFuncAttributeMaxDynamicSharedMemorySize, HSMEM);

    detect_kernel<<<1, 32>>>(ei);
    zero_kernel<<<(NN + 255) / 256, 256>>>(out, cls_b2);
    split_weights_kernel<<<(WTOTAL + 255) / 256, 256>>>(cheb, cls_w1, en_w1, en_w2);

    edge_hmma_kernel<<<148, 512, ESMEM>>>(edgenet, en_b1, en_g1, en_be1, en_b2, ew);

    degcnt_kernel<<<(EE + 255) / 256, 256>>>(ei, ew);
    dis_kernel<<<(NN + 255) / 256, 256>>>();
    scan_kernel<<<1, 1024>>>();
    fill_kernel<<<(EE + 255) / 256, 256>>>(ei, ew);

    const int mtiles = (NN + 127) / 128;
    for (int l = 0; l < 4; l++) {
        const int xsel = (l == 0) ? SEL_EXT : SEL_JK;
        const int xoff = (l == 0) ? 0 : (l - 1) * 256;
        const int ldx  = (l == 0) ? 256 : 1024;
        prop_kernel<<<NN, 64>>>(xsel, features, xoff, ldx,
                                0, nullptr, 0, 0, SEL_T1, 0);
        prop_kernel<<<NN, 64>>>(SEL_T1, nullptr, 0, 256,
                                xsel, features, xoff, ldx, SEL_T2, 1);
        dim3 gC(mtiles, 2);
        hmma_kernel<2><<<gC, 256, HSMEM>>>(
            xsel, features, xoff, ldx,
            (l * 3) * 65536, 3, 8, 256,
            SEL_JK, l * 256, 1024, NN,
            nullptr, nullptr, nullptr, nullptr, nullptr);
    }

    dim3 gZ(mtiles, 2);
    hmma_kernel<1><<<gZ, 256, HSMEM>>>(
        SEL_JK, nullptr, 0, 1024,
        CLS_OFF, 1, 32, 256,
        SEL_JK, 0, 256, NN,
        cls_b1, cls_g, cls_b, cls_w2, out);
}